// round 4
// baseline (speedup 1.0000x reference)
#include <cuda_runtime.h>

// ---------------- problem constants ----------------
#define NFREQ 32
#define EMB   192          // 3 * 32 * 2
#define D0    128
#define D1    256
#define D2    128
#define NC    32
#define NT    4
#define NY    50000
#define NX    32768
#define KNB   8
#define NE    (NX*KNB)     // 262144

#define MT      128        // edges per tile
#define NTILES  (NE/MT)    // 2048

// scratch: first-layer factored precompute
__device__ float g_Ay[NY*D0];   // y_emb @ W0[0:192,:]
__device__ float g_Ax[NX*D0];   // x_emb @ W0[192:384,:] + b0

// ---------------- math helpers ----------------
__device__ __forceinline__ float tanh_acc(float u){
    // accurate tanh via exp (tanh.approx.f32 abs err ~2^-11 is too coarse here)
    float e = __expf(2.0f*u);
    return 1.0f - 2.0f/(e + 1.0f);
}
__device__ __forceinline__ float gelu(float x){
    float u = 0.7978845608028654f*(x + 0.044715f*x*x*x);
    return 0.5f*x*(1.0f + tanh_acc(u));
}

// ---------------- precompute: A_y / A_x ----------------
__global__ void precompute_kernel(const float* __restrict__ y,
                                  const float* __restrict__ x,
                                  const float* __restrict__ W0,
                                  const float* __restrict__ b0)
{
    __shared__ float s_emb[32][EMB];    // 24 KB
    const int nyb = (NY + 31) / 32;
    const bool isY = (int)blockIdx.x < nyb;
    const int row0  = isY ? blockIdx.x*32 : (blockIdx.x - nyb)*32;
    const int nrows = isY ? min(32, NY - row0) : min(32, NX - row0);
    const float* P  = isY ? y : x;
    const float* W  = isY ? W0 : (W0 + EMB*D0);
    float* outp     = isY ? g_Ay : g_Ax;
    const int tid = threadIdx.x;   // 128 threads

    // sinusoidal embedding: emb index j = d*64 + f*2 + {0:sin, 1:cos}
    for (int i = tid; i < nrows*EMB; i += 128) {
        int r = i / EMB, j = i - r*EMB;
        int d = j >> 6;
        int f = (j >> 1) & 31;
        float freq = exp2f(-0.41524101186092029f * (float)f);  // (1e-4)^(f/32)
        float ang  = P[(row0 + r)*3 + d] * freq;
        s_emb[r][j] = (j & 1) ? __cosf(ang) : __sinf(ang);
    }
    __syncthreads();

    const int c = tid;             // output column 0..127
    float acc[32];
#pragma unroll
    for (int r = 0; r < 32; r++) acc[r] = 0.f;

    for (int k = 0; k < EMB; k += 4) {
        float w0 = W[(k+0)*D0 + c];
        float w1 = W[(k+1)*D0 + c];
        float w2 = W[(k+2)*D0 + c];
        float w3 = W[(k+3)*D0 + c];
#pragma unroll
        for (int r = 0; r < 32; r++) {
            float4 e4 = *(const float4*)&s_emb[r][k];
            acc[r] = fmaf(e4.x, w0, acc[r]);
            acc[r] = fmaf(e4.y, w1, acc[r]);
            acc[r] = fmaf(e4.z, w2, acc[r]);
            acc[r] = fmaf(e4.w, w3, acc[r]);
        }
    }
    float bias = isY ? 0.f : b0[c];
#pragma unroll
    for (int r = 0; r < 32; r++)
        if (r < nrows) outp[(row0 + r)*D0 + c] = acc[r] + bias;
}

// ---------------- fused edge-MLP + reduce ----------------
// smem layout (floats):
//   sA  : 128*136  (h1 as [k][m], later h3 as [k][m])
//   sH2 : 64*136   (h2 chunk as [k][m]; later kern as [e][c] stride 33)
//   sW1 : 128*64   (W1 column chunk; later W3)
//   sW2 : 64*128   (W2 row chunk)
//   s_nbr : 128 ints
#define SMEM_FLOATS (17408 + 8704 + 8192 + 8192)
#define SMEM_BYTES  (SMEM_FLOATS*4 + 128*4)   // 170496 B

__global__ void __launch_bounds__(256)
edge_kernel(const int* __restrict__ nbr,
            const float* __restrict__ fy,
            const float* __restrict__ W1, const float* __restrict__ b1,
            const float* __restrict__ W2, const float* __restrict__ b2,
            const float* __restrict__ W3, const float* __restrict__ b3,
            float* __restrict__ out)
{
    extern __shared__ float smem[];
    float* sA   = smem;                      // 17408
    float* sH2  = smem + 17408;              // 8704
    float* sW1  = smem + 17408 + 8704;       // 8192
    float* sW2  = sW1 + 8192;                // 8192
    int*   s_nbr = (int*)(sW2 + 8192);

    const int tile = blockIdx.x;
    const int e0   = tile * MT;
    const int tid  = threadIdx.x;
    const int tx   = tid & 15;
    const int ty   = tid >> 4;
    const int xbase = tile * (MT/KNB);       // 16 x-rows per tile

    if (tid < MT) s_nbr[tid] = nbr[e0 + tid];   // int32 (JAX x64-disabled downcast)
    __syncthreads();

    // phase 0: h1[e][c] = gelu(A_y[nbr[e]][c] + A_x[x(e)][c]), stored [c][e]
    {
        int c = tid & 127;
        int h = tid >> 7;
        for (int e = h; e < MT; e += 2) {
            float v = g_Ay[s_nbr[e]*D0 + c] + g_Ax[(xbase + (e >> 3))*D0 + c];
            sA[c*136 + e] = gelu(v);
        }
    }

    float h3acc[8][8];
#pragma unroll
    for (int i = 0; i < 8; i++)
#pragma unroll
        for (int j = 0; j < 8; j++) h3acc[i][j] = 0.f;

    // K-chunked layer1+layer2: h3 += gelu(h1 @ W1[:,ch]) @ W2[ch,:]
    for (int ch = 0; ch < 4; ch++) {
        __syncthreads();   // prev GEMM2 readers done before overwriting buffers
        for (int i = tid; i < D0*64; i += 256) {
            int k = i >> 6, n = i & 63;
            sW1[i] = W1[k*D1 + ch*64 + n];
        }
        for (int i = tid; i < 64*D2; i += 256) {
            sW2[i] = W2[ch*64*D2 + i];
        }
        __syncthreads();

        // GEMM1 chunk: rows ty*8..+7, cols (tx + 16j) j<4
        float c1[8][4];
#pragma unroll
        for (int i = 0; i < 8; i++)
#pragma unroll
            for (int j = 0; j < 4; j++) c1[i][j] = 0.f;

#pragma unroll 2
        for (int k = 0; k < D0; k++) {
            float4 a0 = *(const float4*)&sA[k*136 + ty*8];
            float4 a1 = *(const float4*)&sA[k*136 + ty*8 + 4];
            float b[4];
#pragma unroll
            for (int j = 0; j < 4; j++) b[j] = sW1[k*64 + tx + 16*j];
            float a[8] = {a0.x,a0.y,a0.z,a0.w,a1.x,a1.y,a1.z,a1.w};
#pragma unroll
            for (int i = 0; i < 8; i++)
#pragma unroll
                for (int j = 0; j < 4; j++)
                    c1[i][j] = fmaf(a[i], b[j], c1[i][j]);
        }
        // bias + gelu -> sH2 [n][m]
#pragma unroll
        for (int j = 0; j < 4; j++) {
            float bb = b1[ch*64 + tx + 16*j];
#pragma unroll
            for (int i = 0; i < 8; i++)
                sH2[(tx + 16*j)*136 + ty*8 + i] = gelu(c1[i][j] + bb);
        }
        __syncthreads();

        // GEMM2 partial: k over this chunk's 64 h2 dims
#pragma unroll 2
        for (int k = 0; k < 64; k++) {
            float4 a0 = *(const float4*)&sH2[k*136 + ty*8];
            float4 a1 = *(const float4*)&sH2[k*136 + ty*8 + 4];
            float b[8];
#pragma unroll
            for (int j = 0; j < 8; j++) b[j] = sW2[k*128 + tx + 16*j];
            float a[8] = {a0.x,a0.y,a0.z,a0.w,a1.x,a1.y,a1.z,a1.w};
#pragma unroll
            for (int i = 0; i < 8; i++)
#pragma unroll
                for (int j = 0; j < 8; j++)
                    h3acc[i][j] = fmaf(a[i], b[j], h3acc[i][j]);
        }
    }

    // h3 = gelu(h3acc + b2) -> sA [k][m]   (all sA readers finished at last
    // mid-chunk barrier; concurrent GEMM2 touches only sH2/sW2)
#pragma unroll
    for (int j = 0; j < 8; j++) {
        float bb = b2[tx + 16*j];
#pragma unroll
        for (int i = 0; i < 8; i++)
            sA[(tx + 16*j)*136 + ty*8 + i] = gelu(h3acc[i][j] + bb);
    }
    // W3 into sW1 region (sW1 also has no remaining readers)
    for (int i = tid; i < D2*NC; i += 256) sW1[i] = W3[i];
    __syncthreads();

    // GEMM3: kern[e][c], rows ty*8..+7, cols tx*2..+1
    float c3[8][2];
#pragma unroll
    for (int i = 0; i < 8; i++) { c3[i][0] = 0.f; c3[i][1] = 0.f; }
#pragma unroll 2
    for (int k = 0; k < D2; k++) {
        float4 a0 = *(const float4*)&sA[k*136 + ty*8];
        float4 a1 = *(const float4*)&sA[k*136 + ty*8 + 4];
        float2 b  = *(const float2*)&sW1[k*NC + tx*2];
        float a[8] = {a0.x,a0.y,a0.z,a0.w,a1.x,a1.y,a1.z,a1.w};
#pragma unroll
        for (int i = 0; i < 8; i++) {
            c3[i][0] = fmaf(a[i], b.x, c3[i][0]);
            c3[i][1] = fmaf(a[i], b.y, c3[i][1]);
        }
    }
    {
        float bx = b3[tx*2], by = b3[tx*2 + 1];
#pragma unroll
        for (int i = 0; i < 8; i++) {
            sH2[(ty*8 + i)*33 + tx*2    ] = c3[i][0] + bx;
            sH2[(ty*8 + i)*33 + tx*2 + 1] = c3[i][1] + by;
        }
    }
    __syncthreads();

    // reduce: out[t, x, c] = sum_{j<8} kern[e][c] * f_y[t, nbr[e], c]
    {
        int wid  = tid >> 5;
        int lane = tid & 31;
        for (int q = wid; q < 64; q += 8) {
            int t = q >> 4;
            int r = q & 15;
            float acc = 0.f;
#pragma unroll
            for (int j = 0; j < KNB; j++) {
                int e = r*KNB + j;
                acc = fmaf(sH2[e*33 + lane],
                           fy[(t*NY + s_nbr[e])*NC + lane], acc);
            }
            out[(t*NX + xbase + r)*NC + lane] = acc;
        }
    }
}

// ---------------- launch ----------------
extern "C" void kernel_launch(void* const* d_in, const int* in_sizes, int n_in,
                              void* d_out, int out_size)
{
    const float* y  = (const float*)d_in[0];
    const float* x  = (const float*)d_in[1];
    const float* fy = (const float*)d_in[2];
    const int*   nbr = (const int*)d_in[3];   // int32! (JAX x64 disabled)
    const float* W0 = (const float*)d_in[4];  const float* b0 = (const float*)d_in[5];
    const float* W1 = (const float*)d_in[6];  const float* b1 = (const float*)d_in[7];
    const float* W2 = (const float*)d_in[8];  const float* b2 = (const float*)d_in[9];
    const float* W3 = (const float*)d_in[10]; const float* b3 = (const float*)d_in[11];
    float* out = (float*)d_out;

    int nyb = (NY + 31) / 32;
    int nxb = (NX + 31) / 32;
    precompute_kernel<<<nyb + nxb, 128>>>(y, x, W0, b0);

    cudaFuncSetAttribute(edge_kernel,
                         cudaFuncAttributeMaxDynamicSharedMemorySize, SMEM_BYTES);
    edge_kernel<<<NTILES, 256, SMEM_BYTES>>>(nbr, fy, W1, b1, W2, b2, W3, b3, out);
}

// round 7
// speedup vs baseline: 1.8564x; 1.8564x over previous
#include <cuda_runtime.h>
#include <cstdint>

// ---------------- problem constants ----------------
#define EMB   192
#define D0    128
#define D1    256
#define D2    128
#define NC    32
#define NT    4
#define NY    50000
#define NX    32768
#define KNB   8
#define NE    (NX*KNB)
#define MT    128
#define NTILES (NE/MT)

// ---------------- global scratch ----------------
__device__ float    g_Ay[NY*D0];
__device__ float    g_Ax[NX*D0];
__device__ uint32_t g_W1img[D0*D1];   // tf32 frag-ordered, per 64-col chunk
__device__ uint32_t g_W2img[D1*D2];   // tf32 frag-ordered, per 64-row chunk
__device__ uint32_t g_W3img[D2*NC];   // tf32 frag-ordered

// ---------------- math ----------------
__device__ __forceinline__ float tanh_acc(float u){
    float e = __expf(2.0f*u);
    return 1.0f - 2.0f/(e + 1.0f);
}
__device__ __forceinline__ float gelu(float x){
    float u = 0.7978845608028654f*(x + 0.044715f*x*x*x);
    return 0.5f*x*(1.0f + tanh_acc(u));
}
__device__ __forceinline__ uint32_t tf32b(float f){
    uint32_t r;
    asm("cvt.rna.tf32.f32 %0, %1;" : "=r"(r) : "f"(f));
    return r;
}
__device__ __forceinline__ void mma8(float c[4], const uint4 a, const uint2 b){
    asm volatile(
        "mma.sync.aligned.m16n8k8.row.col.f32.tf32.tf32.f32 "
        "{%0,%1,%2,%3},{%4,%5,%6,%7},{%8,%9},{%0,%1,%2,%3};"
        : "+f"(c[0]), "+f"(c[1]), "+f"(c[2]), "+f"(c[3])
        : "r"(a.x), "r"(a.y), "r"(a.z), "r"(a.w), "r"(b.x), "r"(b.y));
}

// A-fragment float index inside an [M x K] operand image (M/16 = 8 m-tiles).
// tile (kt, mt) base = (kt*8 + mt)*128; within: lane*4 + reg.
__device__ __forceinline__ int afrag(int row, int col){
    return (((col >> 3)*8 + (row >> 4)) << 7)
         + (((row & 7)*4 + (col & 3)) << 2)
         + ((row >> 3) & 1) + (((col >> 2) & 1) << 1);
}
// B-fragment float index inside an 8x8 tile: lane*2 + (k>>2)
__device__ __forceinline__ int bfrag_idx(int k, int n){
    return (((n & 7)*4 + (k & 3)) << 1) + ((k >> 2) & 1);
}

// ---------------- weight prep: tf32 fragment images ----------------
__global__ void wprep_kernel(const float* __restrict__ W1,
                             const float* __restrict__ W2,
                             const float* __restrict__ W3){
    int i = blockIdx.x*blockDim.x + threadIdx.x;
    if (i < 32768){                 // W1 [k=128][n=256]
        int k = i >> 8, n = i & 255;
        int ch = n >> 6, nt = (n & 63) >> 3, kt = k >> 3;
        int base = ((ch*16 + kt)*8 + nt)*64;
        g_W1img[base + bfrag_idx(k, n)] = tf32b(W1[k*D1 + n]);
    } else if (i < 65536){          // W2 [k=256][n=128]
        int j = i - 32768;
        int k = j >> 7, n = j & 127;
        int ch = k >> 6, kt = (k & 63) >> 3, nt = n >> 3;
        int base = ((ch*8 + kt)*16 + nt)*64;
        g_W2img[base + bfrag_idx(k, n)] = tf32b(W2[k*D2 + n]);
    } else if (i < 69632){          // W3 [k=128][n=32]
        int j = i - 65536;
        int k = j >> 5, n = j & 31;
        int base = ((k >> 3)*4 + (n >> 3))*64;
        g_W3img[base + bfrag_idx(k, n)] = tf32b(W3[k*NC + n]);
    }
}

// ---------------- precompute A_y / A_x (validated) ----------------
__global__ void precompute_kernel(const float* __restrict__ y,
                                  const float* __restrict__ x,
                                  const float* __restrict__ W0,
                                  const float* __restrict__ b0)
{
    __shared__ float s_emb[32][EMB];
    const int nyb = (NY + 31) / 32;
    const bool isY = (int)blockIdx.x < nyb;
    const int row0  = isY ? blockIdx.x*32 : (blockIdx.x - nyb)*32;
    const int nrows = isY ? min(32, NY - row0) : min(32, NX - row0);
    const float* P  = isY ? y : x;
    const float* W  = isY ? W0 : (W0 + EMB*D0);
    float* outp     = isY ? g_Ay : g_Ax;
    const int tid = threadIdx.x;

    for (int i = tid; i < nrows*EMB; i += 128) {
        int r = i / EMB, j = i - r*EMB;
        int d = j >> 6;
        int f = (j >> 1) & 31;
        float freq = exp2f(-0.41524101186092029f * (float)f);
        float ang  = P[(row0 + r)*3 + d] * freq;
        s_emb[r][j] = (j & 1) ? __cosf(ang) : __sinf(ang);
    }
    __syncthreads();

    const int c = tid;
    float acc[32];
#pragma unroll
    for (int r = 0; r < 32; r++) acc[r] = 0.f;
    for (int k = 0; k < EMB; k += 4) {
        float w0 = W[(k+0)*D0 + c], w1 = W[(k+1)*D0 + c];
        float w2 = W[(k+2)*D0 + c], w3 = W[(k+3)*D0 + c];
#pragma unroll
        for (int r = 0; r < 32; r++) {
            float4 e4 = *(const float4*)&s_emb[r][k];
            acc[r] = fmaf(e4.x, w0, acc[r]);
            acc[r] = fmaf(e4.y, w1, acc[r]);
            acc[r] = fmaf(e4.z, w2, acc[r]);
            acc[r] = fmaf(e4.w, w3, acc[r]);
        }
    }
    float bias = isY ? 0.f : b0[c];
#pragma unroll
    for (int r = 0; r < 32; r++)
        if (r < nrows) outp[(row0 + r)*D0 + c] = acc[r] + bias;
}

// ---------------- fused edge kernel (mma.sync tf32) ----------------
// smem (bytes): H1 img 64KB @0 | H2 chunk img 32KB @65536 | sW1 32KB @98304 |
//               sW2 32KB @131072 (reused as s_kern) | misc @163840
#define OFF_H1   0
#define OFF_H2   65536
#define OFF_W1   98304
#define OFF_W2   131072
#define OFF_MISC 163840
#define SMEM_BYTES (163840 + 2304)

__global__ void __launch_bounds__(256, 1)
edge_kernel(const int* __restrict__ nbr, const float* __restrict__ fy,
            const float* __restrict__ b1g, const float* __restrict__ b2g,
            const float* __restrict__ b3g, float* __restrict__ out)
{
    extern __shared__ char sm[];
    uint32_t* sH1 = (uint32_t*)(sm + OFF_H1);
    uint32_t* sH2 = (uint32_t*)(sm + OFF_H2);
    uint32_t* sW1 = (uint32_t*)(sm + OFF_W1);
    uint32_t* sW2 = (uint32_t*)(sm + OFF_W2);
    int*   s_nbr = (int*)(sm + OFF_MISC);
    float* sb1   = (float*)(sm + OFF_MISC + 512);    // 256 floats
    float* sb2   = (float*)(sm + OFF_MISC + 1536);   // 128 floats
    float* sb3   = (float*)(sm + OFF_MISC + 2048);   // 32 floats

    const int tid  = threadIdx.x;
    const int w    = tid >> 5;
    const int lane = tid & 31;
    const int g    = lane >> 2;        // group id (row within tile)
    const int q    = lane & 3;
    const int wr   = w >> 1;           // row-strip 0..3 (32 rows)
    const int wc   = w & 1;            // col-half
    const int mtb  = 2*wr;

    const int tile  = blockIdx.x;
    const int e0    = tile * MT;
    const int xbase = tile * (MT/KNB);

    if (tid < 128) s_nbr[tid] = nbr[e0 + tid];
    sb1[tid] = b1g[tid];
    if (tid < 128) sb2[tid] = b2g[tid];
    if (tid < 32)  sb3[tid] = b3g[tid];
    __syncthreads();

    // ---- gather: h1 = gelu(A_y[nbr] + A_x), stored tf32 frag-ordered ----
    {
        const int c  = tid & 127;
        const int eh = tid >> 7;
        const float* ax = g_Ax + (size_t)xbase*D0 + c;
#pragma unroll 4
        for (int i = 0; i < 64; i++) {
            int e = eh*64 + i;
            float v = g_Ay[(size_t)s_nbr[e]*D0 + c] + ax[(e >> 3)*D0];
            sH1[afrag(e, c)] = tf32b(gelu(v));
        }
    }

    float acc2[2][8][4];
#pragma unroll
    for (int m = 0; m < 2; m++)
#pragma unroll
        for (int n = 0; n < 8; n++)
#pragma unroll
            for (int r = 0; r < 4; r++) acc2[m][n][r] = 0.f;

    // ---- chunk loop over D1 (4 chunks of 64) ----
    for (int ch = 0; ch < 4; ch++) {
        __syncthreads();   // protect sW1/sW2 from previous readers
        {
            const uint4* s1 = (const uint4*)(g_W1img + ch*8192);
            const uint4* s2 = (const uint4*)(g_W2img + ch*8192);
            uint4* d1 = (uint4*)sW1;
            uint4* d2 = (uint4*)sW2;
#pragma unroll
            for (int i = 0; i < 8; i++) d1[tid + 256*i] = s1[tid + 256*i];
#pragma unroll
            for (int i = 0; i < 8; i++) d2[tid + 256*i] = s2[tid + 256*i];
        }
        __syncthreads();

        // GEMM1: h2c[128x64] = h1[128x128] @ W1chunk
        float acc1[2][4][4];
#pragma unroll
        for (int m = 0; m < 2; m++)
#pragma unroll
            for (int n = 0; n < 4; n++)
#pragma unroll
                for (int r = 0; r < 4; r++) acc1[m][n][r] = 0.f;

#pragma unroll 4
        for (int kt = 0; kt < 16; kt++) {
            uint4 a0 = *(const uint4*)(sH1 + (kt*8 + mtb    )*128 + lane*4);
            uint4 a1 = *(const uint4*)(sH1 + (kt*8 + mtb + 1)*128 + lane*4);
#pragma unroll
            for (int nt = 0; nt < 4; nt++) {
                uint2 b = *(const uint2*)(sW1 + (kt*8 + wc*4 + nt)*64 + lane*2);
                mma8(acc1[0][nt], a0, b);
                mma8(acc1[1][nt], a1, b);
            }
        }
        // epilogue1: gelu(+b1) -> sH2 frag-ordered (k = local chunk col)
#pragma unroll
        for (int m = 0; m < 2; m++) {
            int r0 = 32*wr + 16*m + g;
#pragma unroll
            for (int nt = 0; nt < 4; nt++) {
                int cl = wc*32 + nt*8 + 2*q;          // local col in chunk
                float bb0 = sb1[ch*64 + cl], bb1 = sb1[ch*64 + cl + 1];
                sH2[afrag(r0,     cl    )] = tf32b(gelu(acc1[m][nt][0] + bb0));
                sH2[afrag(r0,     cl + 1)] = tf32b(gelu(acc1[m][nt][1] + bb1));
                sH2[afrag(r0 + 8, cl    )] = tf32b(gelu(acc1[m][nt][2] + bb0));
                sH2[afrag(r0 + 8, cl + 1)] = tf32b(gelu(acc1[m][nt][3] + bb1));
            }
        }
        __syncthreads();

        // GEMM2 partial: h3 += h2c[128x64] @ W2chunk[64x128]
#pragma unroll 2
        for (int kt = 0; kt < 8; kt++) {
            uint4 a0 = *(const uint4*)(sH2 + (kt*8 + mtb    )*128 + lane*4);
            uint4 a1 = *(const uint4*)(sH2 + (kt*8 + mtb + 1)*128 + lane*4);
#pragma unroll
            for (int nt = 0; nt < 8; nt++) {
                uint2 b = *(const uint2*)(sW2 + (kt*16 + wc*8 + nt)*64 + lane*2);
                mma8(acc2[0][nt], a0, b);
                mma8(acc2[1][nt], a1, b);
            }
        }
    }

    // ---- epilogue2: h3 = gelu(acc2 + b2) -> sH1 frag-ordered ----
#pragma unroll
    for (int m = 0; m < 2; m++) {
        int r0 = 32*wr + 16*m + g;
#pragma unroll
        for (int nt = 0; nt < 8; nt++) {
            int cg = wc*64 + nt*8 + 2*q;
            float bb0 = sb2[cg], bb1 = sb2[cg + 1];
            sH1[afrag(r0,     cg    )] = tf32b(gelu(acc2[m][nt][0] + bb0));
            sH1[afrag(r0,     cg + 1)] = tf32b(gelu(acc2[m][nt][1] + bb1));
            sH1[afrag(r0 + 8, cg    )] = tf32b(gelu(acc2[m][nt][2] + bb0));
            sH1[afrag(r0 + 8, cg + 1)] = tf32b(gelu(acc2[m][nt][3] + bb1));
        }
    }
    // W3 -> sW1 (its GEMM1 readers all passed the last pre-GEMM2 barrier)
    {
        const uint4* s3 = (const uint4*)g_W3img;
        uint4* d3 = (uint4*)sW1;
#pragma unroll
        for (int i = 0; i < 4; i++) d3[tid + 256*i] = s3[tid + 256*i];
    }
    __syncthreads();

    // ---- GEMM3: kern[128x32] = h3 @ W3 ----
    float acc3[4][4];
#pragma unroll
    for (int n = 0; n < 4; n++)
#pragma unroll
        for (int r = 0; r < 4; r++) acc3[n][r] = 0.f;
#pragma unroll 4
    for (int kt = 0; kt < 16; kt++) {
        uint4 a = *(const uint4*)(sH1 + (kt*8 + w)*128 + lane*4);
#pragma unroll
        for (int nt = 0; nt < 4; nt++) {
            uint2 b = *(const uint2*)(sW1 + (kt*4 + nt)*64 + lane*2);
            mma8(acc3[nt], a, b);
        }
    }
    float* s_kern = (float*)sW2;   // 128*33 floats
    {
        int r0 = 16*w + g;
#pragma unroll
        for (int nt = 0; nt < 4; nt++) {
            int c = nt*8 + 2*q;
            float bb0 = sb3[c], bb1 = sb3[c + 1];
            s_kern[r0*33 + c]           = acc3[nt][0] + bb0;
            s_kern[r0*33 + c + 1]       = acc3[nt][1] + bb1;
            s_kern[(r0 + 8)*33 + c]     = acc3[nt][2] + bb0;
            s_kern[(r0 + 8)*33 + c + 1] = acc3[nt][3] + bb1;
        }
    }
    __syncthreads();

    // ---- reduction: out[t,x,c] = sum_j kern[e][c] * f_y[t, nbr[e], c] ----
    {
        for (int qq = w; qq < 64; qq += 8) {
            int t = qq >> 4, rr = qq & 15;
            float acc = 0.f;
#pragma unroll
            for (int j = 0; j < KNB; j++) {
                int e = rr*KNB + j;
                acc = fmaf(s_kern[e*33 + lane],
                           fy[((size_t)t*NY + s_nbr[e])*NC + lane], acc);
            }
            out[((size_t)t*NX + xbase + rr)*NC + lane] = acc;
        }
    }
}

// ---------------- launch ----------------
extern "C" void kernel_launch(void* const* d_in, const int* in_sizes, int n_in,
                              void* d_out, int out_size)
{
    const float* y  = (const float*)d_in[0];
    const float* x  = (const float*)d_in[1];
    const float* fy = (const float*)d_in[2];
    const int*   nbr = (const int*)d_in[3];
    const float* W0 = (const float*)d_in[4];  const float* b0 = (const float*)d_in[5];
    const float* W1 = (const float*)d_in[6];  const float* b1 = (const float*)d_in[7];
    const float* W2 = (const float*)d_in[8];  const float* b2 = (const float*)d_in[9];
    const float* W3 = (const float*)d_in[10]; const float* b3 = (const float*)d_in[11];
    float* out = (float*)d_out;

    wprep_kernel<<<(69632 + 255)/256, 256>>>(W1, W2, W3);

    int nyb = (NY + 31)/32, nxb = (NX + 31)/32;
    precompute_kernel<<<nyb + nxb, 128>>>(y, x, W0, b0);

    cudaFuncSetAttribute(edge_kernel,
                         cudaFuncAttributeMaxDynamicSharedMemorySize, SMEM_BYTES);
    edge_kernel<<<NTILES, 256, SMEM_BYTES>>>(nbr, fy, b1, b2, b3, out);
}

// round 9
// speedup vs baseline: 2.9227x; 1.5744x over previous
#include <cuda_runtime.h>
#include <cstdint>

// ---------------- problem constants ----------------
#define EMB   192
#define D0    128
#define D1    256
#define D2    128
#define NC    32
#define NT    4
#define NY    50000
#define NX    32768
#define KNB   8
#define NE    (NX*KNB)
#define MT    128
#define NTILES (NE/MT)

// ---------------- global scratch ----------------
__device__ float    g_Ay[NY*D0];
__device__ float    g_Ax[NX*D0];
__device__ uint32_t g_W1img[D0*D1/2];   // fp16x2 frag-ordered (16K u32)
__device__ uint32_t g_W2img[D1*D2/2];   // 16K u32
__device__ uint32_t g_W3img[D2*NC/2];   // 2K u32

// ---------------- math ----------------
__device__ __forceinline__ float tanh_acc(float u){
    float e = __expf(2.0f*u);
    return 1.0f - 2.0f/(e + 1.0f);
}
__device__ __forceinline__ float gelu(float x){
    float u = 0.7978845608028654f*(x + 0.044715f*x*x*x);
    return 0.5f*x*(1.0f + tanh_acc(u));
}
__device__ __forceinline__ uint32_t pack_h2(float lo, float hi){
    uint32_t r;
    asm("cvt.rn.f16x2.f32 %0, %1, %2;" : "=r"(r) : "f"(hi), "f"(lo));
    return r;
}
__device__ __forceinline__ void mma16(float c[4], const uint4 a, const uint2 b){
    asm volatile(
        "mma.sync.aligned.m16n8k16.row.col.f32.f16.f16.f32 "
        "{%0,%1,%2,%3},{%4,%5,%6,%7},{%8,%9},{%0,%1,%2,%3};"
        : "+f"(c[0]), "+f"(c[1]), "+f"(c[2]), "+f"(c[3])
        : "r"(a.x), "r"(a.y), "r"(a.z), "r"(a.w), "r"(b.x), "r"(b.y));
}

// fp16 A-image u32 index, [128 rows x W cols], W/16 ktiles, 8 mtiles.
// tile(kt,mt) base = (kt*8+mt)*128 u32; within: lane*4 + reg; half = col&1.
__device__ __forceinline__ int aidx(int row, int col){
    int tile = (col >> 4)*8 + (row >> 4);
    int lane = (row & 7)*4 + ((col & 7) >> 1);
    int reg  = ((row >> 3) & 1) | (((col >> 3) & 1) << 1);
    return tile*128 + lane*4 + reg;
}

// ---------------- weight prep: fp16 fragment images ----------------
// one thread per packed u32 (covers k and k+1)
__global__ void wprep_kernel(const float* __restrict__ W1,
                             const float* __restrict__ W2,
                             const float* __restrict__ W3){
    int id = blockIdx.x*blockDim.x + threadIdx.x;
    if (id < 16384){                 // W1 [k=128][n=256]
        int t = id >> 6, u = id & 63, lane = u >> 1, reg = u & 1;
        int nt = t & 7, kt = (t >> 3) & 7, ch = t >> 6;
        int n = ch*64 + nt*8 + (lane >> 2);
        int k = kt*16 + reg*8 + (lane & 3)*2;
        g_W1img[id] = pack_h2(W1[k*D1 + n], W1[(k+1)*D1 + n]);
    } else if (id < 32768){          // W2 [k=256][n=128]
        int j = id - 16384;
        int t = j >> 6, u = j & 63, lane = u >> 1, reg = u & 1;
        int nt = t & 15, kt = (t >> 4) & 3, ch = t >> 6;
        int n = nt*8 + (lane >> 2);
        int k = ch*64 + kt*16 + reg*8 + (lane & 3)*2;
        g_W2img[j] = pack_h2(W2[k*D2 + n], W2[(k+1)*D2 + n]);
    } else if (id < 34816){          // W3 [k=128][n=32]
        int j = id - 32768;
        int t = j >> 6, u = j & 63, lane = u >> 1, reg = u & 1;
        int nt = t & 3, kt = t >> 2;
        int n = nt*8 + (lane >> 2);
        int k = kt*16 + reg*8 + (lane & 3)*2;
        g_W3img[j] = pack_h2(W3[k*NC + n], W3[(k+1)*NC + n]);
    }
}

// ---------------- precompute A_y / A_x via fp16 mma ----------------
// smem: sEmb 49152B (12288 u32) | sW0 49152B | sb0 512B
#define PRE_SMEM (49152 + 49152 + 512)
__global__ void __launch_bounds__(256)
precompute_kernel(const float* __restrict__ y, const float* __restrict__ x,
                  const float* __restrict__ W0, const float* __restrict__ b0g)
{
    extern __shared__ char psm[];
    uint32_t* sEmb = (uint32_t*)psm;
    uint32_t* sW0  = (uint32_t*)(psm + 49152);
    float*    sb0  = (float*)(psm + 98304);

    const int nyb = (NY + 127)/128;                 // 391
    const bool isY = (int)blockIdx.x < nyb;
    const int row0  = isY ? blockIdx.x*128 : ((int)blockIdx.x - nyb)*128;
    const int limit = isY ? NY : NX;
    const float* P  = isY ? y : x;
    const float* Wb = isY ? W0 : (W0 + EMB*D0);
    float* outp     = isY ? g_Ay : g_Ax;

    const int tid  = threadIdx.x;
    const int w    = tid >> 5;
    const int lane = tid & 31;
    const int g    = lane >> 2;
    const int q    = lane & 3;

    if (tid < 128) sb0[tid] = isY ? 0.f : b0g[tid];

    // W0 half image: 12 ktiles x 16 ntiles
    for (int idx = tid; idx < 12288; idx += 256){
        int t = idx >> 6, u = idx & 63, ln = u >> 1, reg = u & 1;
        int nt = t & 15, kt = t >> 4;
        int n = nt*8 + (ln >> 2);
        int k = kt*16 + reg*8 + (ln & 3)*2;
        sW0[idx] = pack_h2(Wb[k*D0 + n], Wb[(k+1)*D0 + n]);
    }
    // embedding image: pair (sin, cos) per u32. col pair cp: j=2cp -> d=cp>>5, f=cp&31
    for (int idx = tid; idx < 12288; idx += 256){
        int row = idx / 96, cp = idx - row*96;
        int r = row0 + row; if (r >= limit) r = limit - 1;
        int d = cp >> 5, f = cp & 31;
        float freq = exp2f(-0.41524101186092029f * (float)f);
        float ang = P[r*3 + d] * freq;
        float s, c; __sincosf(ang, &s, &c);
        int tile = (cp >> 3)*8 + (row >> 4);
        int ln   = (row & 7)*4 + (cp & 3);
        int reg  = ((row >> 3) & 1) | (((cp >> 2) & 1) << 1);
        sEmb[tile*128 + ln*4 + reg] = pack_h2(s, c);
    }
    __syncthreads();

    float acc[16][4];
#pragma unroll
    for (int nt = 0; nt < 16; nt++)
#pragma unroll
        for (int r = 0; r < 4; r++) acc[nt][r] = 0.f;

#pragma unroll 3
    for (int kt = 0; kt < 12; kt++){
        uint4 a = *(const uint4*)(sEmb + (kt*8 + w)*128 + lane*4);
#pragma unroll
        for (int nt = 0; nt < 16; nt++){
            uint2 b = *(const uint2*)(sW0 + (kt*16 + nt)*64 + lane*2);
            mma16(acc[nt], a, b);
        }
    }
#pragma unroll
    for (int nt = 0; nt < 16; nt++){
        int c0 = nt*8 + 2*q;
        int r  = w*16 + g;
        if (row0 + r < limit){
            float2 v = make_float2(acc[nt][0] + sb0[c0], acc[nt][1] + sb0[c0+1]);
            *(float2*)(outp + (size_t)(row0 + r)*D0 + c0) = v;
        }
        if (row0 + r + 8 < limit){
            float2 v = make_float2(acc[nt][2] + sb0[c0], acc[nt][3] + sb0[c0+1]);
            *(float2*)(outp + (size_t)(row0 + r + 8)*D0 + c0) = v;
        }
    }
}

// ---------------- persistent fused edge kernel (fp16 mma) ----------------
// smem: sH1 32KB @0 | sH2 2x16KB @32768 (also s_kern) | sW1 64KB @65536 |
//       sW2 64KB @131072 | sW3 8KB @196608 | misc @204800
#define OFF_H1   0
#define OFF_H2   32768
#define OFF_W1   65536
#define OFF_W2   131072
#define OFF_W3   196608
#define OFF_MISC 204800
#define SMEM_BYTES (204800 + 2176)

__global__ void __launch_bounds__(256, 1)
edge_kernel(const int* __restrict__ nbr, const float* __restrict__ fy,
            const float* __restrict__ b1g, const float* __restrict__ b2g,
            const float* __restrict__ b3g, float* __restrict__ out)
{
    extern __shared__ char sm[];
    uint32_t* sH1 = (uint32_t*)(sm + OFF_H1);
    uint32_t* sW1 = (uint32_t*)(sm + OFF_W1);
    uint32_t* sW2 = (uint32_t*)(sm + OFF_W2);
    uint32_t* sW3 = (uint32_t*)(sm + OFF_W3);
    int*   s_nbr = (int*)(sm + OFF_MISC);
    float* sb1   = (float*)(sm + OFF_MISC + 512);
    float* sb2   = (float*)(sm + OFF_MISC + 1536);
    float* sb3   = (float*)(sm + OFF_MISC + 2048);

    const int tid  = threadIdx.x;
    const int w    = tid >> 5;
    const int lane = tid & 31;
    const int g    = lane >> 2;
    const int q    = lane & 3;
    const int wr   = w >> 1;
    const int wc   = w & 1;
    const int mtb  = 2*wr;

    // ---- stage ALL weights + biases once per CTA ----
    {
        const uint4* s1 = (const uint4*)g_W1img;  uint4* d1 = (uint4*)sW1;
        const uint4* s2 = (const uint4*)g_W2img;  uint4* d2 = (uint4*)sW2;
        const uint4* s3 = (const uint4*)g_W3img;  uint4* d3 = (uint4*)sW3;
        for (int i = tid; i < 4096; i += 256) d1[i] = s1[i];
        for (int i = tid; i < 4096; i += 256) d2[i] = s2[i];
        for (int i = tid; i < 512;  i += 256) d3[i] = s3[i];
        sb1[tid] = b1g[tid];
        if (tid < 128) sb2[tid] = b2g[tid];
        if (tid < 32)  sb3[tid] = b3g[tid];
    }
    __syncthreads();

    for (int tile = blockIdx.x; tile < NTILES; tile += gridDim.x){
        const int e0    = tile * MT;
        const int xbase = tile * (MT/KNB);

        if (tid < 128) s_nbr[tid] = nbr[e0 + tid];
        __syncthreads();

        // ---- gather: h1 = gelu(A_y[nbr] + A_x) -> fp16 frag image ----
        {
            const int p   = tid & 63;          // col pair (cols 2p, 2p+1)
            const int grp = tid >> 6;          // 4 groups x 32 edges
            const float* ax = g_Ax + (size_t)xbase*D0 + 2*p;
#pragma unroll 4
            for (int i = 0; i < 32; i++){
                int e = grp*32 + i;
                float2 ay = *(const float2*)(g_Ay + (size_t)s_nbr[e]*D0 + 2*p);
                float2 axv = *(const float2*)(ax + (e >> 3)*D0);
                int tilei = (p >> 3)*8 + (e >> 4);
                int ln    = (e & 7)*4 + (p & 3);
                int reg   = ((e >> 3) & 1) | (((p >> 2) & 1) << 1);
                sH1[tilei*128 + ln*4 + reg] =
                    pack_h2(gelu(ay.x + axv.x), gelu(ay.y + axv.y));
            }
        }
        __syncthreads();

        float acc2[2][8][4];
#pragma unroll
        for (int m = 0; m < 2; m++)
#pragma unroll
            for (int n = 0; n < 8; n++)
#pragma unroll
                for (int r = 0; r < 4; r++) acc2[m][n][r] = 0.f;

        // ---- chunk loop over D1 (4 chunks of 64) ----
        for (int ch = 0; ch < 4; ch++){
            uint32_t* buf = (uint32_t*)(sm + OFF_H2 + (ch & 1)*16384);

            // GEMM1: h2c[128x64] = h1 @ W1[:, ch]
            float acc1[2][4][4];
#pragma unroll
            for (int m = 0; m < 2; m++)
#pragma unroll
                for (int n = 0; n < 4; n++)
#pragma unroll
                    for (int r = 0; r < 4; r++) acc1[m][n][r] = 0.f;

#pragma unroll 2
            for (int kt = 0; kt < 8; kt++){
                uint4 a0 = *(const uint4*)(sH1 + (kt*8 + mtb    )*128 + lane*4);
                uint4 a1 = *(const uint4*)(sH1 + (kt*8 + mtb + 1)*128 + lane*4);
#pragma unroll
                for (int nt = 0; nt < 4; nt++){
                    uint2 b = *(const uint2*)(sW1 + ((ch*8 + kt)*8 + wc*4 + nt)*64 + lane*2);
                    mma16(acc1[0][nt], a0, b);
                    mma16(acc1[1][nt], a1, b);
                }
            }
            // epilogue1 -> buf (128x64 image, local cols)
#pragma unroll
            for (int m = 0; m < 2; m++){
                int r0 = 32*wr + 16*m + g;
#pragma unroll
                for (int nt = 0; nt < 4; nt++){
                    int cl = wc*32 + nt*8 + 2*q;
                    float bb0 = sb1[ch*64 + cl], bb1 = sb1[ch*64 + cl + 1];
                    buf[aidx(r0,     cl)] = pack_h2(gelu(acc1[m][nt][0] + bb0),
                                                    gelu(acc1[m][nt][1] + bb1));
                    buf[aidx(r0 + 8, cl)] = pack_h2(gelu(acc1[m][nt][2] + bb0),
                                                    gelu(acc1[m][nt][3] + bb1));
                }
            }
            __syncthreads();

            // GEMM2 partial: h3 += h2c @ W2[ch, :]
#pragma unroll
            for (int kt = 0; kt < 4; kt++){
                uint4 a0 = *(const uint4*)(buf + (kt*8 + mtb    )*128 + lane*4);
                uint4 a1 = *(const uint4*)(buf + (kt*8 + mtb + 1)*128 + lane*4);
#pragma unroll
                for (int nt = 0; nt < 8; nt++){
                    uint2 b = *(const uint2*)(sW2 + ((ch*4 + kt)*16 + wc*8 + nt)*64 + lane*2);
                    mma16(acc2[0][nt], a0, b);
                    mma16(acc2[1][nt], a1, b);
                }
            }
        }

        // ---- epilogue2: h3 = gelu(acc2 + b2) -> sH1 image ----
#pragma unroll
        for (int m = 0; m < 2; m++){
            int r0 = 32*wr + 16*m + g;
#pragma unroll
            for (int nt = 0; nt < 8; nt++){
                int cg = wc*64 + nt*8 + 2*q;
                float bb0 = sb2[cg], bb1 = sb2[cg + 1];
                sH1[aidx(r0,     cg)] = pack_h2(gelu(acc2[m][nt][0] + bb0),
                                                gelu(acc2[m][nt][1] + bb1));
                sH1[aidx(r0 + 8, cg)] = pack_h2(gelu(acc2[m][nt][2] + bb0),
                                                gelu(acc2[m][nt][3] + bb1));
            }
        }
        __syncthreads();

        // ---- GEMM3: kern[128x32] = h3 @ W3 ----
        float acc3[4][4];
#pragma unroll
        for (int n = 0; n < 4; n++)
#pragma unroll
            for (int r = 0; r < 4; r++) acc3[n][r] = 0.f;
#pragma unroll 2
        for (int kt = 0; kt < 8; kt++){
            uint4 a = *(const uint4*)(sH1 + (kt*8 + w)*128 + lane*4);
#pragma unroll
            for (int nt = 0; nt < 4; nt++){
                uint2 b = *(const uint2*)(sW3 + (kt*4 + nt)*64 + lane*2);
                mma16(acc3[nt], a, b);
            }
        }
        float* s_kern = (float*)(sm + OFF_H2);    // 128x33 fp32
        {
            int r0 = 16*w + g;
#pragma unroll
            for (int nt = 0; nt < 4; nt++){
                int c = nt*8 + 2*q;
                float bb0 = sb3[c], bb1 = sb3[c + 1];
                s_kern[r0*33 + c]           = acc3[nt][0] + bb0;
                s_kern[r0*33 + c + 1]       = acc3[nt][1] + bb1;
                s_kern[(r0 + 8)*33 + c]     = acc3[nt][2] + bb0;
                s_kern[(r0 + 8)*33 + c + 1] = acc3[nt][3] + bb1;
            }
        }
        __syncthreads();

        // ---- reduction: out[t,x,c] = sum_j kern[e][c] * f_y[t, nbr[e], c] ----
        for (int qq = w; qq < 64; qq += 8){
            int t = qq >> 4, rr = qq & 15;
            float acc = 0.f;
#pragma unroll
            for (int j = 0; j < KNB; j++){
                int e = rr*KNB + j;
                acc = fmaf(s_kern[e*33 + lane],
                           fy[((size_t)t*NY + s_nbr[e])*NC + lane], acc);
            }
            out[((size_t)t*NX + xbase + rr)*NC + lane] = acc;
        }
        __syncthreads();   // protect s_nbr / sH1 / s_kern before next tile
    }
}

// ---------------- launch ----------------
extern "C" void kernel_launch(void* const* d_in, const int* in_sizes, int n_in,
                              void* d_out, int out_size)
{
    const float* y  = (const float*)d_in[0];
    const float* x  = (const float*)d_in[1];
    const float* fy = (const float*)d_in[2];
    const int*   nbr = (const int*)d_in[3];
    const float* W0 = (const float*)d_in[4];  const float* b0 = (const float*)d_in[5];
    const float* W1 = (const float*)d_in[6];  const float* b1 = (const float*)d_in[7];
    const float* W2 = (const float*)d_in[8];  const float* b2 = (const float*)d_in[9];
    const float* W3 = (const float*)d_in[10]; const float* b3 = (const float*)d_in[11];
    float* out = (float*)d_out;

    wprep_kernel<<<136, 256>>>(W1, W2, W3);

    int nyb = (NY + 127)/128, nxb = (NX + 127)/128;
    cudaFuncSetAttribute(precompute_kernel,
                         cudaFuncAttributeMaxDynamicSharedMemorySize, PRE_SMEM);
    precompute_kernel<<<nyb + nxb, 256, PRE_SMEM>>>(y, x, W0, b0);

    cudaFuncSetAttribute(edge_kernel,
                         cudaFuncAttributeMaxDynamicSharedMemorySize, SMEM_BYTES);
    edge_kernel<<<152, 256, SMEM_BYTES>>>(nbr, fy, b1, b2, b3, out);
}

// round 10
// speedup vs baseline: 5.3707x; 1.8376x over previous
#include <cuda_runtime.h>
#include <cstdint>

// ---------------- problem constants ----------------
#define EMB   192
#define D0    128
#define D1    256
#define D2    128
#define NC    32
#define NT    4
#define NY    50000
#define NX    32768
#define KNB   8
#define NE    (NX*KNB)
#define MT    128
#define NTILES (NE/MT)

// ---------------- global scratch ----------------
__device__ float    g_Ay[NY*D0];
__device__ float    g_Ax[NX*D0];
__device__ uint32_t g_W1img[D0*D1/2];   // fp16x2 frag-ordered (16K u32)
__device__ uint32_t g_W2img[D1*D2/2];   // 16K u32
__device__ uint32_t g_W3img[D2*NC/2];   // 2K u32

// ---------------- math ----------------
// gelu(x) = x * sigmoid(2u), u = 0.79788456*(x + 0.044715 x^3)
// sigmoid via exp2 (1 MUFU) + fast rcp (1 MUFU); no IEEE div.
__device__ __forceinline__ float gelu(float x){
    float u = x*fmaf(0.0356774081f, x*x, 0.7978845608f);
    float z = exp2f(u * -2.8853900817779268f);     // exp(-2u)
    return __fdividef(x, 1.0f + z);
}
__device__ __forceinline__ uint32_t pack_h2(float lo, float hi){
    uint32_t r;
    asm("cvt.rn.f16x2.f32 %0, %1, %2;" : "=r"(r) : "f"(hi), "f"(lo));
    return r;
}
__device__ __forceinline__ void mma16(float c[4], const uint4 a, const uint2 b){
    asm volatile(
        "mma.sync.aligned.m16n8k16.row.col.f32.f16.f16.f32 "
        "{%0,%1,%2,%3},{%4,%5,%6,%7},{%8,%9},{%0,%1,%2,%3};"
        : "+f"(c[0]), "+f"(c[1]), "+f"(c[2]), "+f"(c[3])
        : "r"(a.x), "r"(a.y), "r"(a.z), "r"(a.w), "r"(b.x), "r"(b.y));
}

// fp16 A-image u32 index, [128 rows x W cols], W/16 ktiles, 8 mtiles.
__device__ __forceinline__ int aidx(int row, int col){
    int tile = (col >> 4)*8 + (row >> 4);
    int lane = (row & 7)*4 + ((col & 7) >> 1);
    int reg  = ((row >> 3) & 1) | (((col >> 3) & 1) << 1);
    return tile*128 + lane*4 + reg;
}

// ---------------- weight prep: fp16 fragment images ----------------
__global__ void wprep_kernel(const float* __restrict__ W1,
                             const float* __restrict__ W2,
                             const float* __restrict__ W3){
    int id = blockIdx.x*blockDim.x + threadIdx.x;
    if (id < 16384){                 // W1 [k=128][n=256]
        int t = id >> 6, u = id & 63, lane = u >> 1, reg = u & 1;
        int nt = t & 7, kt = (t >> 3) & 7, ch = t >> 6;
        int n = ch*64 + nt*8 + (lane >> 2);
        int k = kt*16 + reg*8 + (lane & 3)*2;
        g_W1img[id] = pack_h2(W1[k*D1 + n], W1[(k+1)*D1 + n]);
    } else if (id < 32768){          // W2 [k=256][n=128]
        int j = id - 16384;
        int t = j >> 6, u = j & 63, lane = u >> 1, reg = u & 1;
        int nt = t & 15, kt = (t >> 4) & 3, ch = t >> 6;
        int n = nt*8 + (lane >> 2);
        int k = ch*64 + kt*16 + reg*8 + (lane & 3)*2;
        g_W2img[j] = pack_h2(W2[k*D2 + n], W2[(k+1)*D2 + n]);
    } else if (id < 34816){          // W3 [k=128][n=32]
        int j = id - 32768;
        int t = j >> 6, u = j & 63, lane = u >> 1, reg = u & 1;
        int nt = t & 3, kt = t >> 2;
        int n = nt*8 + (lane >> 2);
        int k = kt*16 + reg*8 + (lane & 3)*2;
        g_W3img[j] = pack_h2(W3[k*NC + n], W3[(k+1)*NC + n]);
    }
}

// ---------------- precompute A_y / A_x via fp16 mma ----------------
#define PRE_SMEM (49152 + 49152 + 512)
__global__ void __launch_bounds__(256)
precompute_kernel(const float* __restrict__ y, const float* __restrict__ x,
                  const float* __restrict__ W0, const float* __restrict__ b0g)
{
    extern __shared__ char psm[];
    uint32_t* sEmb = (uint32_t*)psm;
    uint32_t* sW0  = (uint32_t*)(psm + 49152);
    float*    sb0  = (float*)(psm + 98304);

    const int nyb = (NY + 127)/128;
    const bool isY = (int)blockIdx.x < nyb;
    const int row0  = isY ? blockIdx.x*128 : ((int)blockIdx.x - nyb)*128;
    const int limit = isY ? NY : NX;
    const float* P  = isY ? y : x;
    const float* Wb = isY ? W0 : (W0 + EMB*D0);
    float* outp     = isY ? g_Ay : g_Ax;

    const int tid  = threadIdx.x;
    const int w    = tid >> 5;
    const int lane = tid & 31;
    const int g    = lane >> 2;
    const int q    = lane & 3;

    if (tid < 128) sb0[tid] = isY ? 0.f : b0g[tid];

    for (int idx = tid; idx < 12288; idx += 256){
        int t = idx >> 6, u = idx & 63, ln = u >> 1, reg = u & 1;
        int nt = t & 15, kt = t >> 4;
        int n = nt*8 + (ln >> 2);
        int k = kt*16 + reg*8 + (ln & 3)*2;
        sW0[idx] = pack_h2(Wb[k*D0 + n], Wb[(k+1)*D0 + n]);
    }
    for (int idx = tid; idx < 12288; idx += 256){
        int row = idx / 96, cp = idx - row*96;
        int r = row0 + row; if (r >= limit) r = limit - 1;
        int d = cp >> 5, f = cp & 31;
        float freq = exp2f(-0.41524101186092029f * (float)f);
        float ang = P[r*3 + d] * freq;
        float s, c; __sincosf(ang, &s, &c);
        int tile = (cp >> 3)*8 + (row >> 4);
        int ln   = (row & 7)*4 + (cp & 3);
        int reg  = ((row >> 3) & 1) | (((cp >> 2) & 1) << 1);
        sEmb[tile*128 + ln*4 + reg] = pack_h2(s, c);
    }
    __syncthreads();

    float acc[16][4];
#pragma unroll
    for (int nt = 0; nt < 16; nt++)
#pragma unroll
        for (int r = 0; r < 4; r++) acc[nt][r] = 0.f;

#pragma unroll 3
    for (int kt = 0; kt < 12; kt++){
        uint4 a = *(const uint4*)(sEmb + (kt*8 + w)*128 + lane*4);
#pragma unroll
        for (int nt = 0; nt < 16; nt++){
            uint2 b = *(const uint2*)(sW0 + (kt*16 + nt)*64 + lane*2);
            mma16(acc[nt], a, b);
        }
    }
#pragma unroll
    for (int nt = 0; nt < 16; nt++){
        int c0 = nt*8 + 2*q;
        int r  = w*16 + g;
        if (row0 + r < limit){
            float2 v = make_float2(acc[nt][0] + sb0[c0], acc[nt][1] + sb0[c0+1]);
            *(float2*)(outp + (size_t)(row0 + r)*D0 + c0) = v;
        }
        if (row0 + r + 8 < limit){
            float2 v = make_float2(acc[nt][2] + sb0[c0], acc[nt][3] + sb0[c0+1]);
            *(float2*)(outp + (size_t)(row0 + r + 8)*D0 + c0) = v;
        }
    }
}

// ---------------- persistent fused edge kernel (fp16 mma, 512 thr) -------
// smem: sH1 32KB @0 | sH2 2x16KB @32768 (also s_kern) | sW1 64KB @65536 |
//       sW2 64KB @131072 | sW3 8KB @196608 | misc @204800
#define OFF_H1   0
#define OFF_H2   32768
#define OFF_W1   65536
#define OFF_W2   131072
#define OFF_W3   196608
#define OFF_MISC 204800
#define SMEM_BYTES (204800 + 2176)

__global__ void __launch_bounds__(512, 1)
edge_kernel(const int* __restrict__ nbr, const float* __restrict__ fy,
            const float* __restrict__ b1g, const float* __restrict__ b2g,
            const float* __restrict__ b3g, float* __restrict__ out)
{
    extern __shared__ char sm[];
    uint32_t* sH1 = (uint32_t*)(sm + OFF_H1);
    uint32_t* sW1 = (uint32_t*)(sm + OFF_W1);
    uint32_t* sW2 = (uint32_t*)(sm + OFF_W2);
    uint32_t* sW3 = (uint32_t*)(sm + OFF_W3);
    int*   s_nbr = (int*)(sm + OFF_MISC);
    float* sb1   = (float*)(sm + OFF_MISC + 512);
    float* sb2   = (float*)(sm + OFF_MISC + 1536);
    float* sb3   = (float*)(sm + OFF_MISC + 2048);

    const int tid  = threadIdx.x;
    const int w    = tid >> 5;         // 0..15
    const int lane = tid & 31;
    const int g    = lane >> 2;
    const int q    = lane & 3;
    const int wr   = w >> 2;           // row strip 0..3 (32 rows)
    const int wc   = w & 3;            // col group 0..3
    const int mtb  = 2*wr;

    // ---- stage ALL weights + biases once per CTA ----
    {
        const uint4* s1 = (const uint4*)g_W1img;  uint4* d1 = (uint4*)sW1;
        const uint4* s2 = (const uint4*)g_W2img;  uint4* d2 = (uint4*)sW2;
        const uint4* s3 = (const uint4*)g_W3img;  uint4* d3 = (uint4*)sW3;
        for (int i = tid; i < 4096; i += 512) d1[i] = s1[i];
        for (int i = tid; i < 4096; i += 512) d2[i] = s2[i];
        for (int i = tid; i < 512;  i += 512) d3[i] = s3[i];
        if (tid < 256) sb1[tid] = b1g[tid];
        if (tid < 128) sb2[tid] = b2g[tid];
        if (tid < 32)  sb3[tid] = b3g[tid];
    }
    __syncthreads();

    for (int tile = blockIdx.x; tile < NTILES; tile += gridDim.x){
        const int e0    = tile * MT;
        const int xbase = tile * (MT/KNB);

        if (tid < 128) s_nbr[tid] = nbr[e0 + tid];
        __syncthreads();

        // ---- gather: h1 = gelu(A_y[nbr] + A_x) -> fp16 frag image ----
        {
            const int p   = tid & 63;          // col pair (cols 2p, 2p+1)
            const int grp = tid >> 6;          // 8 groups x 16 edges
            const float* ax = g_Ax + (size_t)xbase*D0 + 2*p;
#pragma unroll 4
            for (int i = 0; i < 16; i++){
                int e = grp*16 + i;
                float2 ay = *(const float2*)(g_Ay + (size_t)s_nbr[e]*D0 + 2*p);
                float2 axv = *(const float2*)(ax + (e >> 3)*D0);
                int tilei = (p >> 3)*8 + (e >> 4);
                int ln    = (e & 7)*4 + (p & 3);
                int reg   = ((e >> 3) & 1) | (((p >> 2) & 1) << 1);
                sH1[tilei*128 + ln*4 + reg] =
                    pack_h2(gelu(ay.x + axv.x), gelu(ay.y + axv.y));
            }
        }
        __syncthreads();

        float acc2[2][4][4];
#pragma unroll
        for (int m = 0; m < 2; m++)
#pragma unroll
            for (int n = 0; n < 4; n++)
#pragma unroll
                for (int r = 0; r < 4; r++) acc2[m][n][r] = 0.f;

        // ---- chunk loop over D1 (4 chunks of 64) ----
        for (int ch = 0; ch < 4; ch++){
            uint32_t* buf = (uint32_t*)(sm + OFF_H2 + (ch & 1)*16384);

            // GEMM1: h2c[128x64] = h1 @ W1[:, ch]; warp: 32 rows x 16 cols
            float acc1[2][2][4];
#pragma unroll
            for (int m = 0; m < 2; m++)
#pragma unroll
                for (int n = 0; n < 2; n++)
#pragma unroll
                    for (int r = 0; r < 4; r++) acc1[m][n][r] = 0.f;

#pragma unroll 2
            for (int kt = 0; kt < 8; kt++){
                uint4 a0 = *(const uint4*)(sH1 + (kt*8 + mtb    )*128 + lane*4);
                uint4 a1 = *(const uint4*)(sH1 + (kt*8 + mtb + 1)*128 + lane*4);
#pragma unroll
                for (int nt = 0; nt < 2; nt++){
                    uint2 b = *(const uint2*)(sW1 + ((ch*8 + kt)*8 + wc*2 + nt)*64 + lane*2);
                    mma16(acc1[0][nt], a0, b);
                    mma16(acc1[1][nt], a1, b);
                }
            }
            // epilogue1 -> buf
#pragma unroll
            for (int m = 0; m < 2; m++){
                int r0 = 32*wr + 16*m + g;
#pragma unroll
                for (int nt = 0; nt < 2; nt++){
                    int cl = wc*16 + nt*8 + 2*q;
                    float bb0 = sb1[ch*64 + cl], bb1 = sb1[ch*64 + cl + 1];
                    buf[aidx(r0,     cl)] = pack_h2(gelu(acc1[m][nt][0] + bb0),
                                                    gelu(acc1[m][nt][1] + bb1));
                    buf[aidx(r0 + 8, cl)] = pack_h2(gelu(acc1[m][nt][2] + bb0),
                                                    gelu(acc1[m][nt][3] + bb1));
                }
            }
            __syncthreads();

            // GEMM2 partial: h3 += h2c @ W2[ch, :]; warp: 32 rows x 32 cols
#pragma unroll
            for (int kt = 0; kt < 4; kt++){
                uint4 a0 = *(const uint4*)(buf + (kt*8 + mtb    )*128 + lane*4);
                uint4 a1 = *(const uint4*)(buf + (kt*8 + mtb + 1)*128 + lane*4);
#pragma unroll
                for (int nt = 0; nt < 4; nt++){
                    uint2 b = *(const uint2*)(sW2 + ((ch*4 + kt)*16 + wc*4 + nt)*64 + lane*2);
                    mma16(acc2[0][nt], a0, b);
                    mma16(acc2[1][nt], a1, b);
                }
            }
        }

        // ---- epilogue2: h3 = gelu(acc2 + b2) -> sH1 image ----
#pragma unroll
        for (int m = 0; m < 2; m++){
            int r0 = 32*wr + 16*m + g;
#pragma unroll
            for (int nt = 0; nt < 4; nt++){
                int cg = wc*32 + nt*8 + 2*q;
                float bb0 = sb2[cg], bb1 = sb2[cg + 1];
                sH1[aidx(r0,     cg)] = pack_h2(gelu(acc2[m][nt][0] + bb0),
                                                gelu(acc2[m][nt][1] + bb1));
                sH1[aidx(r0 + 8, cg)] = pack_h2(gelu(acc2[m][nt][2] + bb0),
                                                gelu(acc2[m][nt][3] + bb1));
            }
        }
        __syncthreads();

        // ---- GEMM3: kern[128x32] = h3 @ W3; warp: 16 rows x 16 cols ----
        const int mt3 = w >> 1;        // 0..7
        const int nh3 = w & 1;         // col half
        float acc3[2][4];
#pragma unroll
        for (int n = 0; n < 2; n++)
#pragma unroll
            for (int r = 0; r < 4; r++) acc3[n][r] = 0.f;
#pragma unroll 2
        for (int kt = 0; kt < 8; kt++){
            uint4 a = *(const uint4*)(sH1 + (kt*8 + mt3)*128 + lane*4);
#pragma unroll
            for (int nt = 0; nt < 2; nt++){
                uint2 b = *(const uint2*)(sW3 + (kt*4 + nh3*2 + nt)*64 + lane*2);
                mma16(acc3[nt], a, b);
            }
        }
        float* s_kern = (float*)(sm + OFF_H2);    // 128x33 fp32
        {
            int r0 = 16*mt3 + g;
#pragma unroll
            for (int nt = 0; nt < 2; nt++){
                int c = nh3*16 + nt*8 + 2*q;
                float bb0 = sb3[c], bb1 = sb3[c + 1];
                s_kern[r0*33 + c]           = acc3[nt][0] + bb0;
                s_kern[r0*33 + c + 1]       = acc3[nt][1] + bb1;
                s_kern[(r0 + 8)*33 + c]     = acc3[nt][2] + bb0;
                s_kern[(r0 + 8)*33 + c + 1] = acc3[nt][3] + bb1;
            }
        }
        __syncthreads();

        // ---- reduction: out[t,x,c] = sum_j kern[e][c] * f_y[t, nbr[e], c] ----
        for (int qq = w; qq < 64; qq += 16){
            int t = qq >> 4, rr = qq & 15;
            float acc = 0.f;
#pragma unroll
            for (int j = 0; j < KNB; j++){
                int e = rr*KNB + j;
                acc = fmaf(s_kern[e*33 + lane],
                           fy[((size_t)t*NY + s_nbr[e])*NC + lane], acc);
            }
            out[((size_t)t*NX + xbase + rr)*NC + lane] = acc;
        }
        __syncthreads();   // protect s_nbr / sH1 / s_kern before next tile
    }
}

// ---------------- launch ----------------
extern "C" void kernel_launch(void* const* d_in, const int* in_sizes, int n_in,
                              void* d_out, int out_size)
{
    const float* y  = (const float*)d_in[0];
    const float* x  = (const float*)d_in[1];
    const float* fy = (const float*)d_in[2];
    const int*   nbr = (const int*)d_in[3];
    const float* W0 = (const float*)d_in[4];  const float* b0 = (const float*)d_in[5];
    const float* W1 = (const float*)d_in[6];  const float* b1 = (const float*)d_in[7];
    const float* W2 = (const float*)d_in[8];  const float* b2 = (const float*)d_in[9];
    const float* W3 = (const float*)d_in[10]; const float* b3 = (const float*)d_in[11];
    float* out = (float*)d_out;

    wprep_kernel<<<136, 256>>>(W1, W2, W3);

    int nyb = (NY + 127)/128, nxb = (NX + 127)/128;
    cudaFuncSetAttribute(precompute_kernel,
                         cudaFuncAttributeMaxDynamicSharedMemorySize, PRE_SMEM);
    precompute_kernel<<<nyb + nxb, 256, PRE_SMEM>>>(y, x, W0, b0);

    cudaFuncSetAttribute(edge_kernel,
                         cudaFuncAttributeMaxDynamicSharedMemorySize, SMEM_BYTES);
    edge_kernel<<<152, 512, SMEM_BYTES>>>(nbr, fy, b1, b2, b3, out);
}

// round 11
// speedup vs baseline: 6.2050x; 1.1553x over previous
#include <cuda_runtime.h>
#include <cstdint>

// ---------------- problem constants ----------------
#define EMB   192
#define D0    128
#define D1    256
#define D2    128
#define NC    32
#define NT    4
#define NY    50000
#define NX    32768
#define KNB   8
#define NE    (NX*KNB)
#define MT    128
#define NTILES (NE/MT)

// ---------------- global scratch ----------------
__device__ float    g_Ay[NY*D0];
__device__ float    g_Ax[NX*D0];
__device__ uint32_t g_W1img[D0*D1/2];   // fp16x2 frag-ordered (16K u32)
__device__ uint32_t g_W2img[D1*D2/2];   // 16K u32
__device__ uint32_t g_W3img[D2*NC/2];   // 2K u32

// ---------------- math ----------------
// gelu(x) = 0.5x(1+tanh(u)), u = 0.79788456*(x + 0.044715 x^3)
// tanh.approx.f32: 1 MUFU, abs err ~2^-10.8 (same order as fp16 storage rounding)
__device__ __forceinline__ float gelu(float x){
    float u = x*fmaf(0.0356774081f, x*x, 0.7978845608f);
    float t;
    asm("tanh.approx.f32 %0, %1;" : "=f"(t) : "f"(u));
    return 0.5f*x*(1.0f + t);
}
__device__ __forceinline__ uint32_t pack_h2(float lo, float hi){
    uint32_t r;
    asm("cvt.rn.f16x2.f32 %0, %1, %2;" : "=r"(r) : "f"(hi), "f"(lo));
    return r;
}
__device__ __forceinline__ void mma16(float c[4], const uint4 a, const uint2 b){
    asm volatile(
        "mma.sync.aligned.m16n8k16.row.col.f32.f16.f16.f32 "
        "{%0,%1,%2,%3},{%4,%5,%6,%7},{%8,%9},{%0,%1,%2,%3};"
        : "+f"(c[0]), "+f"(c[1]), "+f"(c[2]), "+f"(c[3])
        : "r"(a.x), "r"(a.y), "r"(a.z), "r"(a.w), "r"(b.x), "r"(b.y));
}

// fp16 A-image u32 index, [128 rows x W cols], W/16 ktiles, 8 mtiles.
__device__ __forceinline__ int aidx(int row, int col){
    int tile = (col >> 4)*8 + (row >> 4);
    int lane = (row & 7)*4 + ((col & 7) >> 1);
    int reg  = ((row >> 3) & 1) | (((col >> 3) & 1) << 1);
    return tile*128 + lane*4 + reg;
}

// ---------------- weight prep: fp16 fragment images ----------------
__global__ void wprep_kernel(const float* __restrict__ W1,
                             const float* __restrict__ W2,
                             const float* __restrict__ W3){
    int id = blockIdx.x*blockDim.x + threadIdx.x;
    if (id < 16384){                 // W1 [k=128][n=256]
        int t = id >> 6, u = id & 63, lane = u >> 1, reg = u & 1;
        int nt = t & 7, kt = (t >> 3) & 7, ch = t >> 6;
        int n = ch*64 + nt*8 + (lane >> 2);
        int k = kt*16 + reg*8 + (lane & 3)*2;
        g_W1img[id] = pack_h2(W1[k*D1 + n], W1[(k+1)*D1 + n]);
    } else if (id < 32768){          // W2 [k=256][n=128]
        int j = id - 16384;
        int t = j >> 6, u = j & 63, lane = u >> 1, reg = u & 1;
        int nt = t & 15, kt = (t >> 4) & 3, ch = t >> 6;
        int n = nt*8 + (lane >> 2);
        int k = ch*64 + kt*16 + reg*8 + (lane & 3)*2;
        g_W2img[j] = pack_h2(W2[k*D2 + n], W2[(k+1)*D2 + n]);
    } else if (id < 34816){          // W3 [k=128][n=32]
        int j = id - 32768;
        int t = j >> 6, u = j & 63, lane = u >> 1, reg = u & 1;
        int nt = t & 3, kt = t >> 2;
        int n = nt*8 + (lane >> 2);
        int k = kt*16 + reg*8 + (lane & 3)*2;
        g_W3img[j] = pack_h2(W3[k*NC + n], W3[(k+1)*NC + n]);
    }
}

// ---------------- precompute A_y / A_x via fp16 mma ----------------
#define PRE_SMEM (49152 + 49152 + 512)
__global__ void __launch_bounds__(256)
precompute_kernel(const float* __restrict__ y, const float* __restrict__ x,
                  const float* __restrict__ W0, const float* __restrict__ b0g)
{
    extern __shared__ char psm[];
    uint32_t* sEmb = (uint32_t*)psm;
    uint32_t* sW0  = (uint32_t*)(psm + 49152);
    float*    sb0  = (float*)(psm + 98304);

    const int nyb = (NY + 127)/128;
    const bool isY = (int)blockIdx.x < nyb;
    const int row0  = isY ? blockIdx.x*128 : ((int)blockIdx.x - nyb)*128;
    const int limit = isY ? NY : NX;
    const float* P  = isY ? y : x;
    const float* Wb = isY ? W0 : (W0 + EMB*D0);
    float* outp     = isY ? g_Ay : g_Ax;

    const int tid  = threadIdx.x;
    const int w    = tid >> 5;
    const int lane = tid & 31;
    const int g    = lane >> 2;
    const int q    = lane & 3;

    if (tid < 128) sb0[tid] = isY ? 0.f : b0g[tid];

    for (int idx = tid; idx < 12288; idx += 256){
        int t = idx >> 6, u = idx & 63, ln = u >> 1, reg = u & 1;
        int nt = t & 15, kt = t >> 4;
        int n = nt*8 + (ln >> 2);
        int k = kt*16 + reg*8 + (ln & 3)*2;
        sW0[idx] = pack_h2(Wb[k*D0 + n], Wb[(k+1)*D0 + n]);
    }
    for (int idx = tid; idx < 12288; idx += 256){
        int row = idx / 96, cp = idx - row*96;
        int r = row0 + row; if (r >= limit) r = limit - 1;
        int d = cp >> 5, f = cp & 31;
        float freq = exp2f(-0.41524101186092029f * (float)f);
        float ang = P[r*3 + d] * freq;
        float s, c; __sincosf(ang, &s, &c);
        int tile = (cp >> 3)*8 + (row >> 4);
        int ln   = (row & 7)*4 + (cp & 3);
        int reg  = ((row >> 3) & 1) | (((cp >> 2) & 1) << 1);
        sEmb[tile*128 + ln*4 + reg] = pack_h2(s, c);
    }
    __syncthreads();

    float acc[16][4];
#pragma unroll
    for (int nt = 0; nt < 16; nt++)
#pragma unroll
        for (int r = 0; r < 4; r++) acc[nt][r] = 0.f;

#pragma unroll 3
    for (int kt = 0; kt < 12; kt++){
        uint4 a = *(const uint4*)(sEmb + (kt*8 + w)*128 + lane*4);
#pragma unroll
        for (int nt = 0; nt < 16; nt++){
            uint2 b = *(const uint2*)(sW0 + (kt*16 + nt)*64 + lane*2);
            mma16(acc[nt], a, b);
        }
    }
#pragma unroll
    for (int nt = 0; nt < 16; nt++){
        int c0 = nt*8 + 2*q;
        int r  = w*16 + g;
        if (row0 + r < limit){
            float2 v = make_float2(acc[nt][0] + sb0[c0], acc[nt][1] + sb0[c0+1]);
            *(float2*)(outp + (size_t)(row0 + r)*D0 + c0) = v;
        }
        if (row0 + r + 8 < limit){
            float2 v = make_float2(acc[nt][2] + sb0[c0], acc[nt][3] + sb0[c0+1]);
            *(float2*)(outp + (size_t)(row0 + r + 8)*D0 + c0) = v;
        }
    }
}

// ---------------- persistent fused edge kernel (fp16 mma, 1024 thr) ------
// smem: sH1 32KB @0 | sH2 2x16KB @32768 (also s_kern) | sW1 64KB @65536 |
//       sW2 64KB @131072 | sW3 8KB @196608 | misc @204800
#define OFF_H1   0
#define OFF_H2   32768
#define OFF_W1   65536
#define OFF_W2   131072
#define OFF_W3   196608
#define OFF_MISC 204800
#define SMEM_BYTES (204800 + 2176)

__global__ void __launch_bounds__(1024, 1)
edge_kernel(const int* __restrict__ nbr, const float* __restrict__ fy,
            const float* __restrict__ b1g, const float* __restrict__ b2g,
            const float* __restrict__ b3g, float* __restrict__ out)
{
    extern __shared__ char sm[];
    uint32_t* sH1 = (uint32_t*)(sm + OFF_H1);
    uint32_t* sW1 = (uint32_t*)(sm + OFF_W1);
    uint32_t* sW2 = (uint32_t*)(sm + OFF_W2);
    uint32_t* sW3 = (uint32_t*)(sm + OFF_W3);
    int*   s_nbr = (int*)(sm + OFF_MISC);
    float* sb1   = (float*)(sm + OFF_MISC + 512);
    float* sb2   = (float*)(sm + OFF_MISC + 1536);
    float* sb3   = (float*)(sm + OFF_MISC + 2048);

    const int tid  = threadIdx.x;
    const int w    = tid >> 5;         // 0..31
    const int lane = tid & 31;
    const int g    = lane >> 2;
    const int q    = lane & 3;
    const int wr   = w >> 2;           // 16-row strip 0..7 (one m-tile)
    const int wc   = w & 3;            // col group 0..3

    // ---- stage ALL weights + biases once per CTA ----
    {
        const uint4* s1 = (const uint4*)g_W1img;  uint4* d1 = (uint4*)sW1;
        const uint4* s2 = (const uint4*)g_W2img;  uint4* d2 = (uint4*)sW2;
        const uint4* s3 = (const uint4*)g_W3img;  uint4* d3 = (uint4*)sW3;
        for (int i = tid; i < 4096; i += 1024) d1[i] = s1[i];
        for (int i = tid; i < 4096; i += 1024) d2[i] = s2[i];
        for (int i = tid; i < 512;  i += 1024) d3[i] = s3[i];
        if (tid < 256) sb1[tid] = b1g[tid];
        if (tid < 128) sb2[tid] = b2g[tid];
        if (tid < 32)  sb3[tid] = b3g[tid];
    }
    __syncthreads();

    for (int tile = blockIdx.x; tile < NTILES; tile += gridDim.x){
        const int e0    = tile * MT;
        const int xbase = tile * (MT/KNB);

        if (tid < 128) s_nbr[tid] = nbr[e0 + tid];
        __syncthreads();

        // ---- gather: h1 = gelu(A_y[nbr] + A_x) -> fp16 frag image ----
        {
            const int p   = tid & 63;          // col pair (cols 2p, 2p+1)
            const int grp = tid >> 6;          // 16 groups x 8 edges
            const float* ax = g_Ax + (size_t)xbase*D0 + 2*p;
#pragma unroll
            for (int i = 0; i < 8; i++){
                int e = grp*8 + i;
                float2 ay = *(const float2*)(g_Ay + (size_t)s_nbr[e]*D0 + 2*p);
                float2 axv = *(const float2*)(ax + (e >> 3)*D0);
                int tilei = (p >> 3)*8 + (e >> 4);
                int ln    = (e & 7)*4 + (p & 3);
                int reg   = ((e >> 3) & 1) | (((p >> 2) & 1) << 1);
                sH1[tilei*128 + ln*4 + reg] =
                    pack_h2(gelu(ay.x + axv.x), gelu(ay.y + axv.y));
            }
        }
        __syncthreads();

        float acc2[4][4];
#pragma unroll
        for (int n = 0; n < 4; n++)
#pragma unroll
            for (int r = 0; r < 4; r++) acc2[n][r] = 0.f;

        // ---- chunk loop over D1 (4 chunks of 64) ----
        for (int ch = 0; ch < 4; ch++){
            uint32_t* buf = (uint32_t*)(sm + OFF_H2 + (ch & 1)*16384);

            // GEMM1: h2c[128x64] = h1 @ W1[:, ch]; warp: 16 rows x 16 cols
            float acc1[2][4];
#pragma unroll
            for (int n = 0; n < 2; n++)
#pragma unroll
                for (int r = 0; r < 4; r++) acc1[n][r] = 0.f;

#pragma unroll 2
            for (int kt = 0; kt < 8; kt++){
                uint4 a = *(const uint4*)(sH1 + (kt*8 + wr)*128 + lane*4);
#pragma unroll
                for (int nt = 0; nt < 2; nt++){
                    uint2 b = *(const uint2*)(sW1 + ((ch*8 + kt)*8 + wc*2 + nt)*64 + lane*2);
                    mma16(acc1[nt], a, b);
                }
            }
            // epilogue1 -> buf
            {
                int r0 = 16*wr + g;
#pragma unroll
                for (int nt = 0; nt < 2; nt++){
                    int cl = wc*16 + nt*8 + 2*q;
                    float bb0 = sb1[ch*64 + cl], bb1 = sb1[ch*64 + cl + 1];
                    buf[aidx(r0,     cl)] = pack_h2(gelu(acc1[nt][0] + bb0),
                                                    gelu(acc1[nt][1] + bb1));
                    buf[aidx(r0 + 8, cl)] = pack_h2(gelu(acc1[nt][2] + bb0),
                                                    gelu(acc1[nt][3] + bb1));
                }
            }
            __syncthreads();

            // GEMM2 partial: h3 += h2c @ W2[ch, :]; warp: 16 rows x 32 cols
#pragma unroll
            for (int kt = 0; kt < 4; kt++){
                uint4 a = *(const uint4*)(buf + (kt*8 + wr)*128 + lane*4);
#pragma unroll
                for (int nt = 0; nt < 4; nt++){
                    uint2 b = *(const uint2*)(sW2 + ((ch*4 + kt)*16 + wc*4 + nt)*64 + lane*2);
                    mma16(acc2[nt], a, b);
                }
            }
        }

        // ---- epilogue2: h3 = gelu(acc2 + b2) -> sH1 image ----
        {
            int r0 = 16*wr + g;
#pragma unroll
            for (int nt = 0; nt < 4; nt++){
                int cg = wc*32 + nt*8 + 2*q;
                float bb0 = sb2[cg], bb1 = sb2[cg + 1];
                sH1[aidx(r0,     cg)] = pack_h2(gelu(acc2[nt][0] + bb0),
                                                gelu(acc2[nt][1] + bb1));
                sH1[aidx(r0 + 8, cg)] = pack_h2(gelu(acc2[nt][2] + bb0),
                                                gelu(acc2[nt][3] + bb1));
            }
        }
        __syncthreads();

        // ---- GEMM3: kern[128x32] = h3 @ W3; warp: 16 rows x 8 cols ----
        float acc3[4];
#pragma unroll
        for (int r = 0; r < 4; r++) acc3[r] = 0.f;
#pragma unroll 2
        for (int kt = 0; kt < 8; kt++){
            uint4 a = *(const uint4*)(sH1 + (kt*8 + wr)*128 + lane*4);
            uint2 b = *(const uint2*)(sW3 + (kt*4 + wc)*64 + lane*2);
            mma16(acc3, a, b);
        }
        float* s_kern = (float*)(sm + OFF_H2);    // 128x33 fp32
        {
            int r0 = 16*wr + g;
            int c  = wc*8 + 2*q;
            float bb0 = sb3[c], bb1 = sb3[c + 1];
            s_kern[r0*33 + c]           = acc3[0] + bb0;
            s_kern[r0*33 + c + 1]       = acc3[1] + bb1;
            s_kern[(r0 + 8)*33 + c]     = acc3[2] + bb0;
            s_kern[(r0 + 8)*33 + c + 1] = acc3[3] + bb1;
        }
        __syncthreads();

        // ---- reduction: out[t,x,c] = sum_j kern[e][c] * f_y[t, nbr[e], c] ----
        for (int qq = w; qq < 64; qq += 32){
            int t = qq >> 4, rr = qq & 15;
            float acc = 0.f;
#pragma unroll
            for (int j = 0; j < KNB; j++){
                int e = rr*KNB + j;
                acc = fmaf(s_kern[e*33 + lane],
                           fy[((size_t)t*NY + s_nbr[e])*NC + lane], acc);
            }
            out[((size_t)t*NX + xbase + rr)*NC + lane] = acc;
        }
        __syncthreads();   // protect s_nbr / sH1 / s_kern before next tile
    }
}

// ---------------- launch ----------------
extern "C" void kernel_launch(void* const* d_in, const int* in_sizes, int n_in,
                              void* d_out, int out_size)
{
    const float* y  = (const float*)d_in[0];
    const float* x  = (const float*)d_in[1];
    const float* fy = (const float*)d_in[2];
    const int*   nbr = (const int*)d_in[3];
    const float* W0 = (const float*)d_in[4];  const float* b0 = (const float*)d_in[5];
    const float* W1 = (const float*)d_in[6];  const float* b1 = (const float*)d_in[7];
    const float* W2 = (const float*)d_in[8];  const float* b2 = (const float*)d_in[9];
    const float* W3 = (const float*)d_in[10]; const float* b3 = (const float*)d_in[11];
    float* out = (float*)d_out;

    wprep_kernel<<<136, 256>>>(W1, W2, W3);

    int nyb = (NY + 127)/128, nxb = (NX + 127)/128;
    cudaFuncSetAttribute(precompute_kernel,
                         cudaFuncAttributeMaxDynamicSharedMemorySize, PRE_SMEM);
    precompute_kernel<<<nyb + nxb, 256, PRE_SMEM>>>(y, x, W0, b0);

    cudaFuncSetAttribute(edge_kernel,
                         cudaFuncAttributeMaxDynamicSharedMemorySize, SMEM_BYTES);
    edge_kernel<<<152, 1024, SMEM_BYTES>>>(nbr, fy, b1, b2, b3, out);
}

// round 12
// speedup vs baseline: 7.0437x; 1.1352x over previous
#include <cuda_runtime.h>
#include <cstdint>

// ---------------- problem constants ----------------
#define EMB   192
#define D0    128
#define D1    256
#define D2    128
#define NC    32
#define NT    4
#define NY    50000
#define NX    32768
#define KNB   8
#define NE    (NX*KNB)
#define MT    128
#define NTILES (NE/MT)

// ---------------- global scratch ----------------
__device__ float    g_Ay[NY*D0];
__device__ float    g_Ax[NX*D0];
__device__ uint32_t g_W1img[D0*D1/2];   // fp16x2 frag-ordered (16K u32)
__device__ uint32_t g_W2img[D1*D2/2];   // 16K u32
__device__ uint32_t g_W3img[D2*NC/2];   // 2K u32

// ---------------- math ----------------
__device__ __forceinline__ float gelu(float x){
    float u = x*fmaf(0.0356774081f, x*x, 0.7978845608f);
    float t;
    asm("tanh.approx.f32 %0, %1;" : "=f"(t) : "f"(u));
    return 0.5f*x*(1.0f + t);
}
__device__ __forceinline__ uint32_t pack_h2(float lo, float hi){
    uint32_t r;
    asm("cvt.rn.f16x2.f32 %0, %1, %2;" : "=r"(r) : "f"(hi), "f"(lo));
    return r;
}
__device__ __forceinline__ void mma16(float c[4], const uint4 a, const uint2 b){
    asm volatile(
        "mma.sync.aligned.m16n8k16.row.col.f32.f16.f16.f32 "
        "{%0,%1,%2,%3},{%4,%5,%6,%7},{%8,%9},{%0,%1,%2,%3};"
        : "+f"(c[0]), "+f"(c[1]), "+f"(c[2]), "+f"(c[3])
        : "r"(a.x), "r"(a.y), "r"(a.z), "r"(a.w), "r"(b.x), "r"(b.y));
}

// fp16 A-image u32 index, [128 rows x W cols], W/16 ktiles, 8 mtiles.
__device__ __forceinline__ int aidx(int row, int col){
    int tile = (col >> 4)*8 + (row >> 4);
    int lane = (row & 7)*4 + ((col & 7) >> 1);
    int reg  = ((row >> 3) & 1) | (((col >> 3) & 1) << 1);
    return tile*128 + lane*4 + reg;
}

// ---------------- weight prep: fp16 fragment images ----------------
__global__ void wprep_kernel(const float* __restrict__ W1,
                             const float* __restrict__ W2,
                             const float* __restrict__ W3){
    int id = blockIdx.x*blockDim.x + threadIdx.x;
    if (id < 16384){                 // W1 [k=128][n=256]
        int t = id >> 6, u = id & 63, lane = u >> 1, reg = u & 1;
        int nt = t & 7, kt = (t >> 3) & 7, ch = t >> 6;
        int n = ch*64 + nt*8 + (lane >> 2);
        int k = kt*16 + reg*8 + (lane & 3)*2;
        g_W1img[id] = pack_h2(W1[k*D1 + n], W1[(k+1)*D1 + n]);
    } else if (id < 32768){          // W2 [k=256][n=128]
        int j = id - 16384;
        int t = j >> 6, u = j & 63, lane = u >> 1, reg = u & 1;
        int nt = t & 15, kt = (t >> 4) & 3, ch = t >> 6;
        int n = nt*8 + (lane >> 2);
        int k = ch*64 + kt*16 + reg*8 + (lane & 3)*2;
        g_W2img[j] = pack_h2(W2[k*D2 + n], W2[(k+1)*D2 + n]);
    } else if (id < 34816){          // W3 [k=128][n=32]
        int j = id - 32768;
        int t = j >> 6, u = j & 63, lane = u >> 1, reg = u & 1;
        int nt = t & 3, kt = t >> 2;
        int n = nt*8 + (lane >> 2);
        int k = kt*16 + reg*8 + (lane & 3)*2;
        g_W3img[j] = pack_h2(W3[k*NC + n], W3[(k+1)*NC + n]);
    }
}

// ---------------- precompute A_y / A_x via fp16 mma ----------------
#define PRE_SMEM (49152 + 49152 + 512)
__global__ void __launch_bounds__(256)
precompute_kernel(const float* __restrict__ y, const float* __restrict__ x,
                  const float* __restrict__ W0, const float* __restrict__ b0g)
{
    extern __shared__ char psm[];
    uint32_t* sEmb = (uint32_t*)psm;
    uint32_t* sW0  = (uint32_t*)(psm + 49152);
    float*    sb0  = (float*)(psm + 98304);

    const int nyb = (NY + 127)/128;
    const bool isY = (int)blockIdx.x < nyb;
    const int row0  = isY ? blockIdx.x*128 : ((int)blockIdx.x - nyb)*128;
    const int limit = isY ? NY : NX;
    const float* P  = isY ? y : x;
    const float* Wb = isY ? W0 : (W0 + EMB*D0);
    float* outp     = isY ? g_Ay : g_Ax;

    const int tid  = threadIdx.x;
    const int w    = tid >> 5;
    const int lane = tid & 31;
    const int g    = lane >> 2;
    const int q    = lane & 3;

    if (tid < 128) sb0[tid] = isY ? 0.f : b0g[tid];

    for (int idx = tid; idx < 12288; idx += 256){
        int t = idx >> 6, u = idx & 63, ln = u >> 1, reg = u & 1;
        int nt = t & 15, kt = t >> 4;
        int n = nt*8 + (ln >> 2);
        int k = kt*16 + reg*8 + (ln & 3)*2;
        sW0[idx] = pack_h2(Wb[k*D0 + n], Wb[(k+1)*D0 + n]);
    }
    for (int idx = tid; idx < 12288; idx += 256){
        int row = idx / 96, cp = idx - row*96;
        int r = row0 + row; if (r >= limit) r = limit - 1;
        int d = cp >> 5, f = cp & 31;
        float freq = exp2f(-0.41524101186092029f * (float)f);
        float ang = P[r*3 + d] * freq;
        float s, c; __sincosf(ang, &s, &c);
        int tile = (cp >> 3)*8 + (row >> 4);
        int ln   = (row & 7)*4 + (cp & 3);
        int reg  = ((row >> 3) & 1) | (((cp >> 2) & 1) << 1);
        sEmb[tile*128 + ln*4 + reg] = pack_h2(s, c);
    }
    __syncthreads();

    float acc[16][4];
#pragma unroll
    for (int nt = 0; nt < 16; nt++)
#pragma unroll
        for (int r = 0; r < 4; r++) acc[nt][r] = 0.f;

#pragma unroll 3
    for (int kt = 0; kt < 12; kt++){
        uint4 a = *(const uint4*)(sEmb + (kt*8 + w)*128 + lane*4);
#pragma unroll
        for (int nt = 0; nt < 16; nt++){
            uint2 b = *(const uint2*)(sW0 + (kt*16 + nt)*64 + lane*2);
            mma16(acc[nt], a, b);
        }
    }
#pragma unroll
    for (int nt = 0; nt < 16; nt++){
        int c0 = nt*8 + 2*q;
        int r  = w*16 + g;
        if (row0 + r < limit){
            float2 v = make_float2(acc[nt][0] + sb0[c0], acc[nt][1] + sb0[c0+1]);
            *(float2*)(outp + (size_t)(row0 + r)*D0 + c0) = v;
        }
        if (row0 + r + 8 < limit){
            float2 v = make_float2(acc[nt][2] + sb0[c0], acc[nt][3] + sb0[c0+1]);
            *(float2*)(outp + (size_t)(row0 + r + 8)*D0 + c0) = v;
        }
    }
}

// ---------------- persistent fused edge kernel (fp16 mma, 1024 thr) ------
// smem: sH1 32KB @0 | buf 32KB @32768 (also s_kern) | sW1 64KB @65536 |
//       sW2 64KB @131072 | sW3 8KB @196608 | misc @204800
#define OFF_H1   0
#define OFF_H2   32768
#define OFF_W1   65536
#define OFF_W2   131072
#define OFF_W3   196608
#define OFF_MISC 204800
#define SMEM_BYTES (204800 + 2176)

__global__ void __launch_bounds__(1024, 1)
edge_kernel(const int* __restrict__ nbr, const float* __restrict__ fy,
            const float* __restrict__ b1g, const float* __restrict__ b2g,
            const float* __restrict__ b3g, float* __restrict__ out)
{
    extern __shared__ char sm[];
    uint32_t* sH1 = (uint32_t*)(sm + OFF_H1);
    uint32_t* buf = (uint32_t*)(sm + OFF_H2);   // 128x128 h2 image (32 KB)
    uint32_t* sW1 = (uint32_t*)(sm + OFF_W1);
    uint32_t* sW2 = (uint32_t*)(sm + OFF_W2);
    uint32_t* sW3 = (uint32_t*)(sm + OFF_W3);
    int*   s_nbr = (int*)(sm + OFF_MISC);
    float* sb1   = (float*)(sm + OFF_MISC + 512);
    float* sb2   = (float*)(sm + OFF_MISC + 1536);
    float* sb3   = (float*)(sm + OFF_MISC + 2048);

    const int tid  = threadIdx.x;
    const int w    = tid >> 5;         // 0..31
    const int lane = tid & 31;
    const int g    = lane >> 2;
    const int q    = lane & 3;
    const int wr   = w >> 2;           // 16-row strip 0..7 (one m-tile)
    const int wc   = w & 3;            // col group 0..3

    // ---- stage ALL weights + biases once per CTA ----
    {
        const uint4* s1 = (const uint4*)g_W1img;  uint4* d1 = (uint4*)sW1;
        const uint4* s2 = (const uint4*)g_W2img;  uint4* d2 = (uint4*)sW2;
        const uint4* s3 = (const uint4*)g_W3img;  uint4* d3 = (uint4*)sW3;
        for (int i = tid; i < 4096; i += 1024) d1[i] = s1[i];
        for (int i = tid; i < 4096; i += 1024) d2[i] = s2[i];
        for (int i = tid; i < 512;  i += 1024) d3[i] = s3[i];
        if (tid < 256) sb1[tid] = b1g[tid];
        if (tid < 128) sb2[tid] = b2g[tid];
        if (tid < 32)  sb3[tid] = b3g[tid];
    }
    __syncthreads();

    for (int tile = blockIdx.x; tile < NTILES; tile += gridDim.x){
        const int e0    = tile * MT;
        const int xbase = tile * (MT/KNB);

        // ---- gather: h1 = gelu(A_y[nbr] + A_x) -> fp16 frag image ----
        // nbr loaded directly (L1 broadcast); s_nbr written for later phases,
        // made visible by the post-gather barrier.
        if (tid < 128) s_nbr[tid] = nbr[e0 + tid];
        {
            const int p   = tid & 63;          // col pair (cols 2p, 2p+1)
            const int grp = tid >> 6;          // 16 groups x 8 edges
            const float* ax = g_Ax + (size_t)xbase*D0 + 2*p;
#pragma unroll
            for (int i = 0; i < 8; i++){
                int e = grp*8 + i;
                int ne = nbr[e0 + e];
                float2 ay = *(const float2*)(g_Ay + (size_t)ne*D0 + 2*p);
                float2 axv = *(const float2*)(ax + (e >> 3)*D0);
                int tilei = (p >> 3)*8 + (e >> 4);
                int ln    = (e & 7)*4 + (p & 3);
                int reg   = ((e >> 3) & 1) | (((p >> 2) & 1) << 1);
                sH1[tilei*128 + ln*4 + reg] =
                    pack_h2(gelu(ay.x + axv.x), gelu(ay.y + axv.y));
            }
        }
        __syncthreads();

        float acc2[4][4];
#pragma unroll
        for (int n = 0; n < 4; n++)
#pragma unroll
            for (int r = 0; r < 4; r++) acc2[n][r] = 0.f;

        // ---- sweep loop over D1 (2 sweeps of 128 cols) ----
        for (int h = 0; h < 2; h++){
            // GEMM1: h2s[128x128] = h1 @ W1[:, h*128..]; warp: 16 rows x 32 cols
            float acc1[4][4];
#pragma unroll
            for (int n = 0; n < 4; n++)
#pragma unroll
                for (int r = 0; r < 4; r++) acc1[n][r] = 0.f;

            const int ch1 = 2*h + (wc >> 1);       // W1 64-col block
            const int nb1 = (wc & 1)*4;            // ntile base within block
#pragma unroll 2
            for (int kt = 0; kt < 8; kt++){
                uint4 a = *(const uint4*)(sH1 + (kt*8 + wr)*128 + lane*4);
#pragma unroll
                for (int nt = 0; nt < 4; nt++){
                    uint2 b = *(const uint2*)(sW1 + ((ch1*8 + kt)*8 + nb1 + nt)*64 + lane*2);
                    mma16(acc1[nt], a, b);
                }
            }
            // epilogue1 -> buf (local cols 0..127 of this sweep)
            {
                int r0 = 16*wr + g;
#pragma unroll
                for (int nt = 0; nt < 4; nt++){
                    int lc = wc*32 + nt*8 + 2*q;
                    float bb0 = sb1[h*128 + lc], bb1 = sb1[h*128 + lc + 1];
                    buf[aidx(r0,     lc)] = pack_h2(gelu(acc1[nt][0] + bb0),
                                                    gelu(acc1[nt][1] + bb1));
                    buf[aidx(r0 + 8, lc)] = pack_h2(gelu(acc1[nt][2] + bb0),
                                                    gelu(acc1[nt][3] + bb1));
                }
            }
            __syncthreads();

            // GEMM2 partial: h3 += h2s @ W2[h*128.., :]; warp: 16 rows x 32 cols
#pragma unroll 2
            for (int kt2 = 0; kt2 < 8; kt2++){
                uint4 a = *(const uint4*)(buf + (kt2*8 + wr)*128 + lane*4);
                int ch2 = 2*h + (kt2 >> 2);
                int kin = kt2 & 3;
#pragma unroll
                for (int nt = 0; nt < 4; nt++){
                    uint2 b = *(const uint2*)(sW2 + ((ch2*4 + kin)*16 + wc*4 + nt)*64 + lane*2);
                    mma16(acc2[nt], a, b);
                }
            }
            __syncthreads();   // WAR: buf rewritten next sweep (or s_kern later)
        }

        // ---- epilogue2: h3 = gelu(acc2 + b2) -> sH1 image ----
        {
            int r0 = 16*wr + g;
#pragma unroll
            for (int nt = 0; nt < 4; nt++){
                int cg = wc*32 + nt*8 + 2*q;
                float bb0 = sb2[cg], bb1 = sb2[cg + 1];
                sH1[aidx(r0,     cg)] = pack_h2(gelu(acc2[nt][0] + bb0),
                                                gelu(acc2[nt][1] + bb1));
                sH1[aidx(r0 + 8, cg)] = pack_h2(gelu(acc2[nt][2] + bb0),
                                                gelu(acc2[nt][3] + bb1));
            }
        }
        __syncthreads();

        // ---- f_y prefetch (overlaps GEMM3): needs only s_nbr ----
        const int rr = w & 15;
        const int tb = w >> 4;             // t in {tb, tb+2}
        float fyv[2][8];
#pragma unroll
        for (int t2 = 0; t2 < 2; t2++)
#pragma unroll
            for (int j = 0; j < 8; j++)
                fyv[t2][j] = fy[((size_t)(tb + 2*t2)*NY + s_nbr[rr*8 + j])*NC + lane];

        // ---- GEMM3: kern[128x32] = h3 @ W3; warp: 16 rows x 8 cols ----
        float acc3[4];
#pragma unroll
        for (int r = 0; r < 4; r++) acc3[r] = 0.f;
#pragma unroll 2
        for (int kt = 0; kt < 8; kt++){
            uint4 a = *(const uint4*)(sH1 + (kt*8 + wr)*128 + lane*4);
            uint2 b = *(const uint2*)(sW3 + (kt*4 + wc)*64 + lane*2);
            mma16(acc3, a, b);
        }
        float* s_kern = (float*)(sm + OFF_H2);    // 128x33 fp32 (over buf)
        {
            int r0 = 16*wr + g;
            int c  = wc*8 + 2*q;
            float bb0 = sb3[c], bb1 = sb3[c + 1];
            s_kern[r0*33 + c]           = acc3[0] + bb0;
            s_kern[r0*33 + c + 1]       = acc3[1] + bb1;
            s_kern[(r0 + 8)*33 + c]     = acc3[2] + bb0;
            s_kern[(r0 + 8)*33 + c + 1] = acc3[3] + bb1;
        }
        __syncthreads();

        // ---- reduction with prefetched f_y ----
#pragma unroll
        for (int t2 = 0; t2 < 2; t2++){
            float acc = 0.f;
#pragma unroll
            for (int j = 0; j < 8; j++)
                acc = fmaf(s_kern[(rr*8 + j)*33 + lane], fyv[t2][j], acc);
            out[((size_t)(tb + 2*t2)*NX + xbase + rr)*NC + lane] = acc;
        }
        __syncthreads();   // protect s_nbr / sH1 / s_kern before next tile
    }
}

// ---------------- launch ----------------
extern "C" void kernel_launch(void* const* d_in, const int* in_sizes, int n_in,
                              void* d_out, int out_size)
{
    const float* y  = (const float*)d_in[0];
    const float* x  = (const float*)d_in[1];
    const float* fy = (const float*)d_in[2];
    const int*   nbr = (const int*)d_in[3];
    const float* W0 = (const float*)d_in[4];  const float* b0 = (const float*)d_in[5];
    const float* W1 = (const float*)d_in[6];  const float* b1 = (const float*)d_in[7];
    const float* W2 = (const float*)d_in[8];  const float* b2 = (const float*)d_in[9];
    const float* W3 = (const float*)d_in[10]; const float* b3 = (const float*)d_in[11];
    float* out = (float*)d_out;

    wprep_kernel<<<136, 256>>>(W1, W2, W3);

    int nyb = (NY + 127)/128, nxb = (NX + 127)/128;
    cudaFuncSetAttribute(precompute_kernel,
                         cudaFuncAttributeMaxDynamicSharedMemorySize, PRE_SMEM);
    precompute_kernel<<<nyb + nxb, 256, PRE_SMEM>>>(y, x, W0, b0);

    cudaFuncSetAttribute(edge_kernel,
                         cudaFuncAttributeMaxDynamicSharedMemorySize, SMEM_BYTES);
    edge_kernel<<<152, 1024, SMEM_BYTES>>>(nbr, fy, b1, b2, b3, out);
}

// round 13
// speedup vs baseline: 7.0465x; 1.0004x over previous
#include <cuda_runtime.h>
#include <cuda_fp16.h>
#include <cstdint>

// ---------------- problem constants ----------------
#define EMB   192
#define D0    128
#define D1    256
#define D2    128
#define NC    32
#define NT    4
#define NY    50000
#define NX    32768
#define KNB   8
#define NE    (NX*KNB)
#define MT    128
#define NTILES (NE/MT)

// ---------------- global scratch ----------------
__device__ float    g_Ay[NY*D0];
__device__ float    g_Ax[NX*D0];
__device__ uint32_t g_W1img[D0*D1/2];   // fp16x2 frag-ordered (16K u32)
__device__ uint32_t g_W2img[D1*D2/2];   // 16K u32
__device__ uint32_t g_W3img[D2*NC/2];   // 2K u32

// ---------------- math ----------------
__device__ __forceinline__ uint32_t pack_h2(float lo, float hi){
    uint32_t r;
    asm("cvt.rn.f16x2.f32 %0, %1, %2;" : "=r"(r) : "f"(hi), "f"(lo));
    return r;
}
// packed gelu: 2 values per call. 4 h2-ops + 1 MUFU.
__device__ __forceinline__ uint32_t gelu_h2(uint32_t xu){
    __half2 x = *reinterpret_cast<__half2*>(&xu);
    const __half2 c1 = __float2half2_rn(0.7978845608f);
    const __half2 c2 = __float2half2_rn(0.0356774081f);
    __half2 u = __hmul2(x, __hfma2(__hmul2(x, x), c2, c1));
    uint32_t uu = *reinterpret_cast<uint32_t*>(&u), tt;
    asm("tanh.approx.f16x2 %0, %1;" : "=r"(tt) : "r"(uu));
    __half2 t  = *reinterpret_cast<__half2*>(&tt);
    __half2 hx = __hmul2(x, __float2half2_rn(0.5f));
    __half2 r  = __hfma2(hx, t, hx);
    return *reinterpret_cast<uint32_t*>(&r);
}
__device__ __forceinline__ uint32_t hadd2u(uint32_t a, uint32_t b){
    uint32_t r;
    asm("add.rn.f16x2 %0, %1, %2;" : "=r"(r) : "r"(a), "r"(b));
    return r;
}
__device__ __forceinline__ void mma16(float c[4], const uint4 a, const uint2 b){
    asm volatile(
        "mma.sync.aligned.m16n8k16.row.col.f32.f16.f16.f32 "
        "{%0,%1,%2,%3},{%4,%5,%6,%7},{%8,%9},{%0,%1,%2,%3};"
        : "+f"(c[0]), "+f"(c[1]), "+f"(c[2]), "+f"(c[3])
        : "r"(a.x), "r"(a.y), "r"(a.z), "r"(a.w), "r"(b.x), "r"(b.y));
}

// fp16 A-image u32 index, [128 rows x W cols], W/16 ktiles, 8 mtiles.
__device__ __forceinline__ int aidx(int row, int col){
    int tile = (col >> 4)*8 + (row >> 4);
    int lane = (row & 7)*4 + ((col & 7) >> 1);
    int reg  = ((row >> 3) & 1) | (((col >> 3) & 1) << 1);
    return tile*128 + lane*4 + reg;
}

// ---------------- weight prep: fp16 fragment images ----------------
__global__ void wprep_kernel(const float* __restrict__ W1,
                             const float* __restrict__ W2,
                             const float* __restrict__ W3){
    int id = blockIdx.x*blockDim.x + threadIdx.x;
    if (id < 16384){                 // W1 [k=128][n=256]
        int t = id >> 6, u = id & 63, lane = u >> 1, reg = u & 1;
        int nt = t & 7, kt = (t >> 3) & 7, ch = t >> 6;
        int n = ch*64 + nt*8 + (lane >> 2);
        int k = kt*16 + reg*8 + (lane & 3)*2;
        g_W1img[id] = pack_h2(W1[k*D1 + n], W1[(k+1)*D1 + n]);
    } else if (id < 32768){          // W2 [k=256][n=128]
        int j = id - 16384;
        int t = j >> 6, u = j & 63, lane = u >> 1, reg = u & 1;
        int nt = t & 15, kt = (t >> 4) & 3, ch = t >> 6;
        int n = nt*8 + (lane >> 2);
        int k = ch*64 + kt*16 + reg*8 + (lane & 3)*2;
        g_W2img[j] = pack_h2(W2[k*D2 + n], W2[(k+1)*D2 + n]);
    } else if (id < 34816){          // W3 [k=128][n=32]
        int j = id - 32768;
        int t = j >> 6, u = j & 63, lane = u >> 1, reg = u & 1;
        int nt = t & 3, kt = t >> 2;
        int n = nt*8 + (lane >> 2);
        int k = kt*16 + reg*8 + (lane & 3)*2;
        g_W3img[j] = pack_h2(W3[k*NC + n], W3[(k+1)*NC + n]);
    }
}

// ---------------- precompute A_y / A_x via fp16 mma ----------------
#define PRE_SMEM (49152 + 49152 + 512)
__global__ void __launch_bounds__(256)
precompute_kernel(const float* __restrict__ y, const float* __restrict__ x,
                  const float* __restrict__ W0, const float* __restrict__ b0g)
{
    extern __shared__ char psm[];
    uint32_t* sEmb = (uint32_t*)psm;
    uint32_t* sW0  = (uint32_t*)(psm + 49152);
    float*    sb0  = (float*)(psm + 98304);

    const int nyb = (NY + 127)/128;
    const bool isY = (int)blockIdx.x < nyb;
    const int row0  = isY ? blockIdx.x*128 : ((int)blockIdx.x - nyb)*128;
    const int limit = isY ? NY : NX;
    const float* P  = isY ? y : x;
    const float* Wb = isY ? W0 : (W0 + EMB*D0);
    float* outp     = isY ? g_Ay : g_Ax;

    const int tid  = threadIdx.x;
    const int w    = tid >> 5;
    const int lane = tid & 31;
    const int g    = lane >> 2;
    const int q    = lane & 3;

    if (tid < 128) sb0[tid] = isY ? 0.f : b0g[tid];

    for (int idx = tid; idx < 12288; idx += 256){
        int t = idx >> 6, u = idx & 63, ln = u >> 1, reg = u & 1;
        int nt = t & 15, kt = t >> 4;
        int n = nt*8 + (ln >> 2);
        int k = kt*16 + reg*8 + (ln & 3)*2;
        sW0[idx] = pack_h2(Wb[k*D0 + n], Wb[(k+1)*D0 + n]);
    }
    for (int idx = tid; idx < 12288; idx += 256){
        int row = idx / 96, cp = idx - row*96;
        int r = row0 + row; if (r >= limit) r = limit - 1;
        int d = cp >> 5, f = cp & 31;
        float freq = exp2f(-0.41524101186092029f * (float)f);
        float ang = P[r*3 + d] * freq;
        float s, c; __sincosf(ang, &s, &c);
        int tile = (cp >> 3)*8 + (row >> 4);
        int ln   = (row & 7)*4 + (cp & 3);
        int reg  = ((row >> 3) & 1) | (((cp >> 2) & 1) << 1);
        sEmb[tile*128 + ln*4 + reg] = pack_h2(s, c);
    }
    __syncthreads();

    float acc[16][4];
#pragma unroll
    for (int nt = 0; nt < 16; nt++)
#pragma unroll
        for (int r = 0; r < 4; r++) acc[nt][r] = 0.f;

#pragma unroll 3
    for (int kt = 0; kt < 12; kt++){
        uint4 a = *(const uint4*)(sEmb + (kt*8 + w)*128 + lane*4);
#pragma unroll
        for (int nt = 0; nt < 16; nt++){
            uint2 b = *(const uint2*)(sW0 + (kt*16 + nt)*64 + lane*2);
            mma16(acc[nt], a, b);
        }
    }
#pragma unroll
    for (int nt = 0; nt < 16; nt++){
        int c0 = nt*8 + 2*q;
        int r  = w*16 + g;
        if (row0 + r < limit){
            float2 v = make_float2(acc[nt][0] + sb0[c0], acc[nt][1] + sb0[c0+1]);
            *(float2*)(outp + (size_t)(row0 + r)*D0 + c0) = v;
        }
        if (row0 + r + 8 < limit){
            float2 v = make_float2(acc[nt][2] + sb0[c0], acc[nt][3] + sb0[c0+1]);
            *(float2*)(outp + (size_t)(row0 + r + 8)*D0 + c0) = v;
        }
    }
}

// ---------------- persistent fused edge kernel (fp16 mma, 1024 thr) ------
// smem: sH1 32KB @0 | buf 32KB @32768 (also s_kern) | sW1 64KB @65536 |
//       sW2 64KB @131072 | sW3 8KB @196608 | misc @204800
#define OFF_H1   0
#define OFF_H2   32768
#define OFF_W1   65536
#define OFF_W2   131072
#define OFF_W3   196608
#define OFF_MISC 204800
#define SMEM_BYTES (204800 + 1536)

__global__ void __launch_bounds__(1024, 1)
edge_kernel(const int* __restrict__ nbr, const float* __restrict__ fy,
            const float* __restrict__ b1g, const float* __restrict__ b2g,
            const float* __restrict__ b3g, float* __restrict__ out)
{
    extern __shared__ char sm[];
    uint32_t* sH1 = (uint32_t*)(sm + OFF_H1);
    uint32_t* buf = (uint32_t*)(sm + OFF_H2);   // 128x128 h2 image (32 KB)
    uint32_t* sW1 = (uint32_t*)(sm + OFF_W1);
    uint32_t* sW2 = (uint32_t*)(sm + OFF_W2);
    uint32_t* sW3 = (uint32_t*)(sm + OFF_W3);
    int*      s_nbr = (int*)(sm + OFF_MISC);                 // 128 ints
    uint32_t* sb1h  = (uint32_t*)(sm + OFF_MISC + 512);      // 128 h2 pairs
    uint32_t* sb2h  = (uint32_t*)(sm + OFF_MISC + 1024);     // 64 h2 pairs
    float*    sb3   = (float*)(sm + OFF_MISC + 1280);        // 32 fp32

    const int tid  = threadIdx.x;
    const int w    = tid >> 5;         // 0..31
    const int lane = tid & 31;
    const int g    = lane >> 2;
    const int q    = lane & 3;
    const int wr2  = w >> 3;           // 32-row strip 0..3 (GEMM1/2)
    const int wc2  = w & 7;            // 16-col group 0..7
    const int wr3  = w >> 2;           // GEMM3: 16-row strip 0..7
    const int wc3  = w & 3;            // GEMM3: 8-col group 0..3

    // ---- stage ALL weights + biases once per CTA ----
    {
        const uint4* s1 = (const uint4*)g_W1img;  uint4* d1 = (uint4*)sW1;
        const uint4* s2 = (const uint4*)g_W2img;  uint4* d2 = (uint4*)sW2;
        const uint4* s3 = (const uint4*)g_W3img;  uint4* d3 = (uint4*)sW3;
        for (int i = tid; i < 4096; i += 1024) d1[i] = s1[i];
        for (int i = tid; i < 4096; i += 1024) d2[i] = s2[i];
        for (int i = tid; i < 512;  i += 1024) d3[i] = s3[i];
        if (tid < 128) sb1h[tid] = pack_h2(b1g[2*tid], b1g[2*tid + 1]);
        else if (tid < 192) sb2h[tid - 128] = pack_h2(b2g[2*(tid-128)], b2g[2*(tid-128) + 1]);
        else if (tid < 224) sb3[tid - 192] = b3g[tid - 192];
    }
    __syncthreads();

    for (int tile = blockIdx.x; tile < NTILES; tile += gridDim.x){
        const int e0    = tile * MT;
        const int xbase = tile * (MT/KNB);

        // ---- gather: h1 = gelu(A_y[nbr] + A_x) -> fp16 frag image ----
        if (tid < 128) s_nbr[tid] = nbr[e0 + tid];
        {
            const int p   = tid & 63;          // col pair (cols 2p, 2p+1)
            const int grp = tid >> 6;          // 16 groups x 8 edges
            const float* ax = g_Ax + (size_t)xbase*D0 + 2*p;
#pragma unroll
            for (int i = 0; i < 8; i++){
                int e = grp*8 + i;
                int ne = nbr[e0 + e];
                float2 ay = *(const float2*)(g_Ay + (size_t)ne*D0 + 2*p);
                float2 axv = *(const float2*)(ax + (e >> 3)*D0);
                int tilei = (p >> 3)*8 + (e >> 4);
                int ln    = (e & 7)*4 + (p & 3);
                int reg   = ((e >> 3) & 1) | (((p >> 2) & 1) << 1);
                sH1[tilei*128 + ln*4 + reg] =
                    gelu_h2(pack_h2(ay.x + axv.x, ay.y + axv.y));
            }
        }
        __syncthreads();

        float acc2[2][2][4];
#pragma unroll
        for (int m = 0; m < 2; m++)
#pragma unroll
            for (int n = 0; n < 2; n++)
#pragma unroll
                for (int r = 0; r < 4; r++) acc2[m][n][r] = 0.f;

        // ---- sweep loop over D1 (2 sweeps of 128 cols) ----
        for (int h = 0; h < 2; h++){
            // GEMM1: h2s[128x128] = h1 @ W1[:, h*128..]; warp: 32 rows x 16 cols
            float acc1[2][2][4];
#pragma unroll
            for (int m = 0; m < 2; m++)
#pragma unroll
                for (int n = 0; n < 2; n++)
#pragma unroll
                    for (int r = 0; r < 4; r++) acc1[m][n][r] = 0.f;

#pragma unroll 2
            for (int kt = 0; kt < 8; kt++){
                uint4 a0 = *(const uint4*)(sH1 + (kt*8 + 2*wr2    )*128 + lane*4);
                uint4 a1 = *(const uint4*)(sH1 + (kt*8 + 2*wr2 + 1)*128 + lane*4);
#pragma unroll
                for (int nt = 0; nt < 2; nt++){
                    int gn = h*16 + wc2*2 + nt;            // global 8-col tile
                    uint2 b = *(const uint2*)(sW1 + (((gn >> 3)*8 + kt)*8 + (gn & 7))*64 + lane*2);
                    mma16(acc1[0][nt], a0, b);
                    mma16(acc1[1][nt], a1, b);
                }
            }
            // epilogue1 -> buf (local cols of this sweep)
            {
#pragma unroll
                for (int m = 0; m < 2; m++){
                    int r0 = 32*wr2 + 16*m + g;
#pragma unroll
                    for (int nt = 0; nt < 2; nt++){
                        int lc = wc2*16 + nt*8 + 2*q;
                        uint32_t bb = sb1h[(h*128 + lc) >> 1];
                        buf[aidx(r0,     lc)] = gelu_h2(hadd2u(
                            pack_h2(acc1[m][nt][0], acc1[m][nt][1]), bb));
                        buf[aidx(r0 + 8, lc)] = gelu_h2(hadd2u(
                            pack_h2(acc1[m][nt][2], acc1[m][nt][3]), bb));
                    }
                }
            }
            __syncthreads();

            // GEMM2 partial: h3 += h2s @ W2[h*128.., :]; warp: 32 rows x 16 cols
#pragma unroll 2
            for (int kt2 = 0; kt2 < 8; kt2++){
                uint4 a0 = *(const uint4*)(buf + (kt2*8 + 2*wr2    )*128 + lane*4);
                uint4 a1 = *(const uint4*)(buf + (kt2*8 + 2*wr2 + 1)*128 + lane*4);
                int gk = h*8 + kt2;                        // global 16-k tile
#pragma unroll
                for (int nt = 0; nt < 2; nt++){
                    int n = wc2*2 + nt;
                    uint2 b = *(const uint2*)(sW2 + (((gk >> 2)*4 + (gk & 3))*16 + n)*64 + lane*2);
                    mma16(acc2[0][nt], a0, b);
                    mma16(acc2[1][nt], a1, b);
                }
            }
            __syncthreads();   // WAR: buf rewritten next sweep (or s_kern later)
        }

        // ---- epilogue2: h3 = gelu(acc2 + b2) -> sH1 image ----
        {
#pragma unroll
            for (int m = 0; m < 2; m++){
                int r0 = 32*wr2 + 16*m + g;
#pragma unroll
                for (int nt = 0; nt < 2; nt++){
                    int cg = wc2*16 + nt*8 + 2*q;
                    uint32_t bb = sb2h[cg >> 1];
                    sH1[aidx(r0,     cg)] = gelu_h2(hadd2u(
                        pack_h2(acc2[m][nt][0], acc2[m][nt][1]), bb));
                    sH1[aidx(r0 + 8, cg)] = gelu_h2(hadd2u(
                        pack_h2(acc2[m][nt][2], acc2[m][nt][3]), bb));
                }
            }
        }
        __syncthreads();

        // ---- f_y prefetch (overlaps GEMM3): needs only s_nbr ----
        const int rr = w & 15;
        const int tb = w >> 4;             // t in {tb, tb+2}
        float fyv[2][8];
#pragma unroll
        for (int t2 = 0; t2 < 2; t2++)
#pragma unroll
            for (int j = 0; j < 8; j++)
                fyv[t2][j] = fy[((size_t)(tb + 2*t2)*NY + s_nbr[rr*8 + j])*NC + lane];

        // ---- GEMM3: kern[128x32] = h3 @ W3; warp: 16 rows x 8 cols ----
        float acc3[4];
#pragma unroll
        for (int r = 0; r < 4; r++) acc3[r] = 0.f;
#pragma unroll 2
        for (int kt = 0; kt < 8; kt++){
            uint4 a = *(const uint4*)(sH1 + (kt*8 + wr3)*128 + lane*4);
            uint2 b = *(const uint2*)(sW3 + (kt*4 + wc3)*64 + lane*2);
            mma16(acc3, a, b);
        }
        float* s_kern = (float*)(sm + OFF_H2);    // 128x33 fp32 (over buf)
        {
            int r0 = 16*wr3 + g;
            int c  = wc3*8 + 2*q;
            float bb0 = sb3[c], bb1 = sb3[c + 1];
            s_kern[r0*33 + c]           = acc3[0] + bb0;
            s_kern[r0*33 + c + 1]       = acc3[1] + bb1;
            s_kern[(r0 + 8)*33 + c]     = acc3[2] + bb0;
            s_kern[(r0 + 8)*33 + c + 1] = acc3[3] + bb1;
        }
        __syncthreads();

        // ---- reduction with prefetched f_y ----
#pragma unroll
        for (int t2 = 0; t2 < 2; t2++){
            float acc = 0.f;
#pragma unroll
            for (int j = 0; j < 8; j++)
                acc = fmaf(s_kern[(rr*8 + j)*33 + lane], fyv[t2][j], acc);
            out[((size_t)(tb + 2*t2)*NX + xbase + rr)*NC + lane] = acc;
        }
        __syncthreads();   // protect s_nbr / sH1 / s_kern before next tile
    }
}

// ---------------- launch ----------------
extern "C" void kernel_launch(void* const* d_in, const int* in_sizes, int n_in,
                              void* d_out, int out_size)
{
    const float* y  = (const float*)d_in[0];
    const float* x  = (const float*)d_in[1];
    const float* fy = (const float*)d_in[2];
    const int*   nbr = (const int*)d_in[3];
    const float* W0 = (const float*)d_in[4];  const float* b0 = (const float*)d_in[5];
    const float* W1 = (const float*)d_in[6];  const float* b1 = (const float*)d_in[7];
    const float* W2 = (const float*)d_in[8];  const float* b2 = (const float*)d_in[9];
    const float* W3 = (const float*)d_in[10]; const float* b3 = (const float*)d_in[11];
    float* out = (float*)d_out;

    wprep_kernel<<<136, 256>>>(W1, W2, W3);

    int nyb = (NY + 127)/128, nxb = (NX + 127)/128;
    cudaFuncSetAttribute(precompute_kernel,
                         cudaFuncAttributeMaxDynamicSharedMemorySize, PRE_SMEM);
    precompute_kernel<<<nyb + nxb, 256, PRE_SMEM>>>(y, x, W0, b0);

    cudaFuncSetAttribute(edge_kernel,
                         cudaFuncAttributeMaxDynamicSharedMemorySize, SMEM_BYTES);
    edge_kernel<<<152, 1024, SMEM_BYTES>>>(nbr, fy, b1, b2, b3, out);
}